// round 14
// baseline (speedup 1.0000x reference)
#include <cuda_runtime.h>
#include <cuda_fp16.h>
#include <cfloat>

#define NN   8192
#define FEA  192
#define HID  256
#define CLS  1000
#define KNB  9
#define KSTR 512
#define BATCH 16
#define LCAP 128

typedef unsigned int u32;
typedef unsigned short u16;
typedef unsigned long long u64;
typedef __half f16;

// ---------------- scratch ----------------------------------------------------
__device__ float g_sq[NN];
__device__ __half g_Dh[(long long)NN * NN];        // 128 MB approx distances
__device__ __half g_tmin[NN * 128];                // per-row per-64col-halfblock minima
__device__ int   g_idx[NN * KNB];
__device__ f16   g_c0h[NN * KSTR];                 // cat buffer 0: [agg | self]
__device__ f16   g_c1h[NN * KSTR];                 // cat buffer 1
__device__ f16   g_w0h[256 * 384],  g_w0l[256 * 384];
__device__ f16   g_w1h[256 * 512],  g_w1l[256 * 512];
__device__ f16   g_w2h[1024 * 512];                // layer2: hi term only
__device__ float g_part[1024 * 128];               // layer2 pool partials

// ---------------- helpers ----------------------------------------------------
__device__ __forceinline__ u32 s2u(const void* p) {
    u32 a;
    asm("{.reg .u64 t; cvta.to.shared.u64 t, %1; cvt.u32.u64 %0, t;}" : "=r"(a) : "l"(p));
    return a;
}
__device__ __forceinline__ void cpa16(u32 dst, const void* src) {
    asm volatile("cp.async.cg.shared.global [%0], [%1], 16;" :: "r"(dst), "l"(src));
}
__device__ __forceinline__ void ldsm4(u32* r, u32 addr) {
    asm volatile("ldmatrix.sync.aligned.m8n8.x4.shared.b16 {%0,%1,%2,%3}, [%4];"
        : "=r"(r[0]), "=r"(r[1]), "=r"(r[2]), "=r"(r[3]) : "r"(addr));
}
__device__ __forceinline__ void mma16816(float* c, const u32* a, const u32* b) {
    asm volatile("mma.sync.aligned.m16n8k16.row.col.f32.f16.f16.f32 "
        "{%0,%1,%2,%3},{%4,%5,%6,%7},{%8,%9},{%0,%1,%2,%3};"
        : "+f"(c[0]), "+f"(c[1]), "+f"(c[2]), "+f"(c[3])
        : "r"(a[0]), "r"(a[1]), "r"(a[2]), "r"(a[3]), "r"(b[0]), "r"(b[1]));
}
__device__ __forceinline__ void spltw(float v, f16& h, f16& l) {
    h = __float2half_rn(v);
    l = __float2half_rn(v - __half2float(h));
}
__device__ __forceinline__ u32 okey(u32 hb) {
    return (hb & 0x8000u) ? (hb ^ 0xFFFFu) : (hb | 0x8000u);
}

// fp16 tile loader: [128 rows x 32 k] (row stride 40 halfs = 80B)
__device__ __forceinline__ void ldtile(u32 dstb, const f16* g, int row0, int ld, int k0, int t) {
    #pragma unroll
    for (int q = 0; q < 2; q++) {
        int id = t * 2 + q;
        int row = id >> 2, kq = id & 3;
        cpa16(dstb + row * 80 + kq * 16, g + (size_t)(row0 + row) * ld + k0 + kq * 8);
    }
}
// fp16 tile loader: [64 rows x 32 k]
__device__ __forceinline__ void ldtileA64(u32 dstb, const f16* g, int row0, int ld, int k0, int t) {
    int row = t >> 2, kq = t & 3;
    cpa16(dstb + row * 80 + kq * 16, g + (size_t)(row0 + row) * ld + k0 + kq * 8);
}

#define TB 10240     // 128-row fp16 tile
#define ATB 5120     // 64-row fp16 tile
#define SSTG (ATB + 2 * TB)   // sage stage = 25600
#define DSTG (ATB + TB)       // dist stage = 15360

// ---------------- fused sq + fp16 pack -----------------------------------------
__global__ void sqprep_kernel(const float* __restrict__ x) {
    int warp = (blockIdx.x * blockDim.x + threadIdx.x) >> 5;
    int lane = threadIdx.x & 31;
    if (warp >= NN) return;
    const float* r = x + (size_t)warp * FEA;
    float s = 0.f;
    #pragma unroll
    for (int q = 0; q < 2; q++) {
        int c4 = (lane + 32 * q) * 4;
        if (c4 < FEA) {
            float4 v = *(const float4*)(r + c4);
            s += v.x * v.x + v.y * v.y + v.z * v.z + v.w * v.w;
            __half2 p0; p0.x = __float2half_rn(v.x); p0.y = __float2half_rn(v.y);
            __half2 p1; p1.x = __float2half_rn(v.z); p1.y = __float2half_rn(v.w);
            size_t off = (size_t)warp * KSTR + 192 + c4;
            *(__half2*)(g_c0h + off)     = p0;
            *(__half2*)(g_c0h + off + 2) = p1;
        }
    }
    #pragma unroll
    for (int o = 16; o; o >>= 1) s += __shfl_xor_sync(0xffffffffu, s, o);
    if (lane == 0) g_sq[warp] = s;
}

__global__ void wt_build01(const float* __restrict__ Wl0, const float* __restrict__ Wr0,
                           const float* __restrict__ Wl1, const float* __restrict__ Wr1) {
    int layer = blockIdx.y;
    const float* Wl = layer ? Wl1 : Wl0;
    const float* Wr = layer ? Wr1 : Wr0;
    f16* WTh = layer ? g_w1h : g_w0h;
    f16* WTl = layer ? g_w1l : g_w0l;
    int K1 = layer ? 256 : 192;
    int Ktot = 2 * K1;
    int total = 256 * Ktot;
    int idx = blockIdx.x * 256 + threadIdx.x;
    if (idx >= total) return;
    int k = idx % Ktot;
    int n = idx / Ktot;
    float v = (k < K1) ? Wl[(size_t)k * HID + n] : Wr[(size_t)(k - K1) * HID + n];
    f16 h, l; spltw(v, h, l);
    WTh[idx] = h; WTl[idx] = l;
}

__global__ void wt_build2(const float* __restrict__ Wl, const float* __restrict__ Wr) {
    int idx = blockIdx.x * 256 + threadIdx.x;
    if (idx >= 1024 * 512) return;
    int n = idx / 512, k = idx % 512;
    float v = 0.f;
    if (n < CLS) v = (k < 256) ? Wl[(size_t)k * CLS + n] : Wr[(size_t)(k - 256) * CLS + n];
    g_w2h[idx] = __float2half_rn(v);
}

// ---------------- fp16 distance screen GEMM, M64 tiles, 3 CTAs/SM ---------------
// grid = 4160: pair tile tp (bi<=bj over 64 blocks) x row-half h
__global__ __launch_bounds__(256, 3) void dist_m64(const f16* __restrict__ Xh) {
    int tp = blockIdx.x >> 1, h = blockIdx.x & 1;
    int bj = (int)((sqrtf(8.f * tp + 1.f) - 1.f) * 0.5f);
    while ((bj + 1) * (bj + 2) / 2 <= tp) bj++;
    while (bj * (bj + 1) / 2 > tp) bj--;
    int bi = tp - bj * (bj + 1) / 2;
    int row0 = bi * 128 + h * 64;     // 64 A-rows

    extern __shared__ __align__(16) char smem[];
    u32 sb = s2u(smem);
    int t = threadIdx.x, lane = t & 31, warp = t >> 5;
    int wm = warp & 1, wn = warp >> 1;

    float acc[2][4][4] = {};

    const int NC = FEA / 32;   // 6
    ldtileA64(sb + 0, Xh, row0, KSTR, 0, t);
    ldtile(sb + ATB, Xh, bj * 128, KSTR, 0, t);
    asm volatile("cp.async.commit_group;");

    for (int c = 0; c < NC; c++) {
        if (c + 1 < NC) {
            u32 bb = sb + ((c + 1) & 1) * DSTG;
            int k0 = (c + 1) * 32;
            ldtileA64(bb + 0, Xh, row0, KSTR, k0, t);
            ldtile(bb + ATB, Xh, bj * 128, KSTR, k0, t);
            asm volatile("cp.async.commit_group;");
            asm volatile("cp.async.wait_group 1;");
        } else {
            asm volatile("cp.async.wait_group 0;");
        }
        __syncthreads();
        u32 base = sb + (c & 1) * DSTG;
        u32 aH = base, bH = base + ATB;
        #pragma unroll
        for (int kk = 0; kk < 32; kk += 16) {
            u32 AH[2][4], BH[4][2];
            #pragma unroll
            for (int mt = 0; mt < 2; mt++) {
                u32 ro = (u32)((wm * 32 + mt * 16 + (lane & 15)) * 80 + (kk + (lane >> 4) * 8) * 2);
                ldsm4(AH[mt], aH + ro);
            }
            #pragma unroll
            for (int np = 0; np < 2; np++) {
                u32 ro = (u32)((wn * 32 + np * 16 + ((lane >> 4) * 8) + (lane & 7)) * 80
                               + (kk + ((lane >> 3) & 1) * 8) * 2);
                u32 r[4];
                ldsm4(r, bH + ro);
                BH[2 * np][0] = r[0]; BH[2 * np][1] = r[1];
                BH[2 * np + 1][0] = r[2]; BH[2 * np + 1][1] = r[3];
            }
            #pragma unroll
            for (int mt = 0; mt < 2; mt++)
                #pragma unroll
                for (int nt = 0; nt < 4; nt++)
                    mma16816(acc[mt][nt], AH[mt], BH[nt]);
        }
        __syncthreads();
    }

    // epilogue: d = sq_i + sq_j - 2*dot; stage direct (64x136) + transposed (128x72)
    u16* sD = (u16*)smem;                    // 64 x 136
    u16* sT = sD + 64 * 136;                 // 128 x 72
    bool diag = (bi == bj);
    #pragma unroll
    for (int mt = 0; mt < 2; mt++) {
        int rl0 = wm * 32 + mt * 16 + (lane >> 2);
        #pragma unroll
        for (int nt = 0; nt < 4; nt++) {
            int cl = wn * 32 + nt * 8 + (lane & 3) * 2;
            float sqc0 = g_sq[bj * 128 + cl], sqc1 = g_sq[bj * 128 + cl + 1];
            #pragma unroll
            for (int hh = 0; hh < 2; hh++) {
                int rl = rl0 + hh * 8;
                float sr = g_sq[row0 + rl];
                float d0 = sr + sqc0 - 2.f * acc[mt][nt][2 * hh + 0];
                float d1 = sr + sqc1 - 2.f * acc[mt][nt][2 * hh + 1];
                u16 b0 = __half_as_ushort(__float2half_rn(d0));
                u16 b1 = __half_as_ushort(__float2half_rn(d1));
                sD[rl * 136 + cl] = b0;
                sD[rl * 136 + cl + 1] = b1;
                if (!diag) {
                    sT[cl * 72 + rl] = b0;
                    sT[(cl + 1) * 72 + rl] = b1;
                }
            }
        }
    }
    __syncthreads();
    u16* gD = (u16*)g_Dh;
    // direct: 64 rows x 128 cols
    #pragma unroll
    for (int q = 0; q < 4; q++) {
        int e = t + q * 256;                 // 1024 uint4
        int r = e >> 4, c8 = (e & 15) * 8;
        uint4 v = *(uint4*)&sD[r * 136 + c8];
        *(uint4*)(gD + (size_t)(row0 + r) * NN + bj * 128 + c8) = v;
    }
    // tmin direct: 64 rows x 2 half-blocks (128 threads active)
    if (t < 128) {
        int r = t >> 1, hf = t & 1;
        const __half2* pr = (const __half2*)(sD + r * 136 + hf * 64);
        __half2 m2 = pr[0];
        #pragma unroll
        for (int q = 1; q < 32; q++) m2 = __hmin2(m2, pr[q]);
        float fm = fminf(__half2float(__low2half(m2)), __half2float(__high2half(m2)));
        g_tmin[(size_t)(row0 + r) * 128 + bj * 2 + hf] = __float2half(fm);
    }
    if (!diag) {
        // transposed: 128 rows x 64 cols
        #pragma unroll
        for (int q = 0; q < 4; q++) {
            int e = t + q * 256;             // 1024 uint4
            int r = e >> 3, c8 = (e & 7) * 8;
            uint4 v = *(uint4*)&sT[r * 72 + c8];
            *(uint4*)(gD + (size_t)(bj * 128 + r) * NN + row0 + c8) = v;
        }
        // tmin transposed: 128 rows x 1 half-block (2 threads/row)
        {
            int r = t >> 1, hf = t & 1;
            const __half2* pr = (const __half2*)(sT + r * 72 + hf * 32);
            __half2 m2 = pr[0];
            #pragma unroll
            for (int q = 1; q < 16; q++) m2 = __hmin2(m2, pr[q]);
            float fm = fminf(__half2float(__low2half(m2)), __half2float(__high2half(m2)));
            float fo = __shfl_xor_sync(0xffffffffu, fm, 1);
            if (hf == 0)
                g_tmin[(size_t)(bj * 128 + r) * 128 + bi * 2 + h] = __float2half(fminf(fm, fo));
        }
    }
}

// ---------------- warp-per-row: tile-min threshold screen + exact refine -------
__global__ __launch_bounds__(256, 6) void topk_warp(const float* __restrict__ x) {
    int lane = threadIdx.x & 31, wid = threadIdx.x >> 5;
    int row = blockIdx.x * 8 + wid;

    __shared__ u32 slist[8][LCAP];
    __shared__ float scd[8][LCAP];
    __shared__ int scnt[8];

    if (lane == 0) scnt[wid] = 0;
    __syncwarp();

    // ---- Phase A: threshold = 16th smallest of the 128 half-block mins ----
    const u16* tm = (const u16*)(g_tmin + (size_t)row * 128);
    u32 kk4[4];
    #pragma unroll
    for (int q = 0; q < 4; q++) {
        u32 e = okey((u32)tm[lane + 32 * q]);
        kk4[q] = (e << 7) | (u32)(lane + 32 * q);
    }
    u32 m16 = 0;
    #pragma unroll
    for (int r = 0; r < 16; r++) {
        u32 mn = min(min(kk4[0], kk4[1]), min(kk4[2], kk4[3]));
        #pragma unroll
        for (int o = 16; o; o >>= 1) mn = min(mn, __shfl_xor_sync(0xffffffffu, mn, o));
        m16 = mn;
        #pragma unroll
        for (int q = 0; q < 4; q++) if (kk4[q] == mn) kk4[q] = 0xFFFFFFFFu;
    }
    u32 thr_key = m16 >> 7;
    u32 thr_hb = (thr_key & 0x8000u) ? (thr_key ^ 0x8000u) : (thr_key ^ 0xFFFFu);
    __half2 thr2 = __half2half2(__ushort_as_half((u16)thr_hb));

    // ---- Phase B: filtered stream, collect candidates <= threshold ----
    const uint4* rp = (const uint4*)(g_Dh + (size_t)row * NN);
    for (int i = 0; i < 32; i++) {
        uint4 v = __ldg(rp + i * 32 + lane);
        union { u32 u; __half2 h; } a0, a1, a2, a3;
        a0.u = v.x; a1.u = v.y; a2.u = v.z; a3.u = v.w;
        __half2 mm = __hmin2(__hmin2(a0.h, a1.h), __hmin2(a2.h, a3.h));
        union { __half2 h; u32 u; } cc; cc.h = __hle2(mm, thr2);
        bool need = (cc.u != 0);
        if (__ballot_sync(0xffffffffu, need)) {
            if (need) {
                u32 w[4] = {v.x, v.y, v.z, v.w};
                u32 base = (u32)((i * 32 + lane) * 8);
                #pragma unroll
                for (int p = 0; p < 4; p++) {
                    #pragma unroll
                    for (int hh = 0; hh < 2; hh++) {
                        u32 key = okey((w[p] >> (16 * hh)) & 0xFFFFu);
                        if (key <= thr_key) {
                            int pos = atomicAdd(&scnt[wid], 1);
                            if (pos < LCAP)
                                slist[wid][pos] = (key << 16) | (base + p * 2 + hh);
                        }
                    }
                }
            }
        }
    }
    __syncwarp();
    int cnt = min(scnt[wid], LCAP);

    // ---- Phase C: exact fp32 refine of all candidates ----
    float xi[6];
    const float* xr = x + (size_t)row * FEA;
    #pragma unroll
    for (int q = 0; q < 6; q++) xi[q] = __ldg(xr + q * 32 + lane);
    float sqi = g_sq[row];
    for (int c = 0; c < cnt; c++) {
        int j = (int)(slist[wid][c] & 0xFFFFu);
        const float* xj = x + (size_t)j * FEA;
        float s = 0.f;
        #pragma unroll
        for (int q = 0; q < 6; q++) s = fmaf(xi[q], __ldg(xj + q * 32 + lane), s);
        #pragma unroll
        for (int o = 16; o; o >>= 1) s += __shfl_xor_sync(0xffffffffu, s, o);
        if (lane == 0) scd[wid][c] = sqi + g_sq[j] - 2.f * s;
    }
    __syncwarp();

    // ---- Phase D: exact top-9 by (fp32 dist, idx) ----
    u64 mykeys[4];
    #pragma unroll
    for (int q = 0; q < 4; q++) {
        int c = lane + 32 * q;
        if (c < cnt) {
            u32 b = __float_as_uint(scd[wid][c]);
            b ^= (b & 0x80000000u) ? 0xFFFFFFFFu : 0x80000000u;
            mykeys[q] = ((u64)b << 32) | (u32)(slist[wid][c] & 0xFFFFu);
        } else {
            mykeys[q] = ~0ull;
        }
    }
    #pragma unroll
    for (int r = 0; r < KNB; r++) {
        u64 mn = mykeys[0];
        #pragma unroll
        for (int q = 1; q < 4; q++) mn = mykeys[q] < mn ? mykeys[q] : mn;
        #pragma unroll
        for (int o = 16; o; o >>= 1) {
            u64 other = __shfl_xor_sync(0xffffffffu, mn, o);
            mn = other < mn ? other : mn;
        }
        if (lane == 0) g_idx[row * KNB + r] = (int)(mn & 0xFFFFFFFFull);
        #pragma unroll
        for (int q = 0; q < 4; q++) if (mykeys[q] == mn) mykeys[q] = ~0ull;
        __syncwarp();
    }
}

// ---------------- gather + mean from fp32 x (layer 0) --------------------------
__global__ void gather_x(const float* __restrict__ x, f16* __restrict__ oh) {
    int row = blockIdx.x * 4 + threadIdx.y;
    int c4 = threadIdx.x * 4;
    const int* idp = g_idx + row * KNB;
    float4 s = make_float4(0.f, 0.f, 0.f, 0.f);
    #pragma unroll
    for (int j = 0; j < KNB; j++) {
        float4 v = __ldg((const float4*)(x + (size_t)idp[j] * FEA + c4));
        s.x += v.x; s.y += v.y; s.z += v.z; s.w += v.w;
    }
    const float inv = 1.0f / 9.0f;
    size_t off = (size_t)row * KSTR + c4;
    __half2 p0; p0.x = __float2half_rn(s.x * inv); p0.y = __float2half_rn(s.y * inv);
    __half2 p1; p1.x = __float2half_rn(s.z * inv); p1.y = __float2half_rn(s.w * inv);
    *(__half2*)(oh + off)     = p0;
    *(__half2*)(oh + off + 2) = p1;
}

// ---------------- gather + mean from fp16 cat self (layers 1,2) ----------------
__global__ void gather_f16(const f16* __restrict__ cat_self, f16* __restrict__ cat_agg) {
    int row = blockIdx.x * 8 + threadIdx.y;
    int c8 = threadIdx.x * 8;
    const int* idp = g_idx + row * KNB;
    float s[8] = {0.f, 0.f, 0.f, 0.f, 0.f, 0.f, 0.f, 0.f};
    #pragma unroll
    for (int j = 0; j < KNB; j++) {
        uint4 v = __ldg((const uint4*)(cat_self + (size_t)idp[j] * KSTR + c8));
        u32 w[4] = {v.x, v.y, v.z, v.w};
        #pragma unroll
        for (int p = 0; p < 4; p++) {
            float2 f = __half22float2(*(__half2*)&w[p]);
            s[2 * p] += f.x; s[2 * p + 1] += f.y;
        }
    }
    const float inv = 1.0f / 9.0f;
    u32 out[4];
    #pragma unroll
    for (int p = 0; p < 4; p++) {
        __half2 h; h.x = __float2half_rn(s[2 * p] * inv); h.y = __float2half_rn(s[2 * p + 1] * inv);
        out[p] = *(u32*)&h;
    }
    *(uint4*)(cat_agg + (size_t)row * KSTR + c8) = *(uint4*)out;
}

// ---------------- SAGE dual-GEMM, M64 tiles, 3 CTAs/SM --------------------------
template <bool TWOTERM>
__global__ __launch_bounds__(256, 3) void sage_mma(
    const f16* __restrict__ Ah, int Ktot,
    const f16* __restrict__ Bh, const f16* __restrict__ Bl,
    const float* __restrict__ bias, int Nbias,
    f16* __restrict__ Sh, float* __restrict__ part)
{
    int bn = blockIdx.x, bm = blockIdx.y;
    extern __shared__ __align__(16) char smem[];
    u32 sb = s2u(smem);
    int t = threadIdx.x, lane = t & 31, warp = t >> 5;
    int wm = warp & 1, wn = warp >> 1;

    float acc[2][4][4] = {};

    int nc = Ktot / 32;
    ldtileA64(sb + 0, Ah, bm * 64, KSTR, 0, t);
    ldtile(sb + ATB, Bh, bn * 128, Ktot, 0, t);
    if (TWOTERM) ldtile(sb + ATB + TB, Bl, bn * 128, Ktot, 0, t);
    asm volatile("cp.async.commit_group;");

    for (int c = 0; c < nc; c++) {
        if (c + 1 < nc) {
            u32 bb = sb + ((c + 1) & 1) * SSTG;
            int k0 = (c + 1) * 32;
            ldtileA64(bb + 0, Ah, bm * 64, KSTR, k0, t);
            ldtile(bb + ATB, Bh, bn * 128, Ktot, k0, t);
            if (TWOTERM) ldtile(bb + ATB + TB, Bl, bn * 128, Ktot, k0, t);
            asm volatile("cp.async.commit_group;");
            asm volatile("cp.async.wait_group 1;");
        } else {
            asm volatile("cp.async.wait_group 0;");
        }
        __syncthreads();
        u32 base = sb + (c & 1) * SSTG;
        u32 aH = base, bH = base + ATB, bL = base + ATB + TB;
        #pragma unroll
        for (int kk = 0; kk < 32; kk += 16) {
            u32 AH[2][4], BH[4][2], BL[4][2];
            #pragma unroll
            for (int mt = 0; mt < 2; mt++) {
                u32 ro = (u32)((wm * 32 + mt * 16 + (lane & 15)) * 80 + (kk + (lane >> 4) * 8) * 2);
                ldsm4(AH[mt], aH + ro);
            }
            #pragma unroll
            for (int np = 0; np < 2; np++) {
                u32 ro = (u32)((wn * 32 + np * 16 + ((lane >> 4) * 8) + (lane & 7)) * 80
                               + (kk + ((lane >> 3) & 1) * 8) * 2);
                u32 r[4];
                ldsm4(r, bH + ro);
                BH[2 * np][0] = r[0]; BH[2 * np][1] = r[1];
                BH[2 * np + 1][0] = r[2]; BH[2 * np + 1][1] = r[3];
                if (TWOTERM) {
                    ldsm4(r, bL + ro);
                    BL[2 * np][0] = r[0]; BL[2 * np][1] = r[1];
                    BL[2 * np + 1][0] = r[2]; BL[2 * np + 1][1] = r[3];
                }
            }
            #pragma unroll
            for (int mt = 0; mt < 2; mt++)
                #pragma unroll
                for (int nt = 0; nt < 4; nt++) {
                    mma16816(acc[mt][nt], AH[mt], BH[nt]);
                    if (TWOTERM) mma16816(acc[mt][nt], AH[mt], BL[nt]);
                }
        }
        __syncthreads();
    }

    if (Sh) {
        #pragma unroll
        for (int mt = 0; mt < 2; mt++) {
            int rl0 = wm * 32 + mt * 16 + (lane >> 2);
            #pragma unroll
            for (int nt = 0; nt < 4; nt++) {
                int cl = wn * 32 + nt * 8 + (lane & 3) * 2;
                int col = bn * 128 + cl;
                float b0 = bias[col], b1 = bias[col + 1];
                #pragma unroll
                for (int h = 0; h < 2; h++) {
                    int row = bm * 64 + rl0 + h * 8;
                    float v0 = fmaxf(acc[mt][nt][2 * h + 0] + b0, 0.f);
                    float v1 = fmaxf(acc[mt][nt][2 * h + 1] + b1, 0.f);
                    __half2 p; p.x = __float2half_rn(v0); p.y = __float2half_rn(v1);
                    *(__half2*)(Sh + (size_t)row * KSTR + col) = p;
                }
            }
        }
    } else {
        float* sCol = (float*)smem;
        if (t < 128) sCol[t] = 0.f;
        __syncthreads();
        #pragma unroll
        for (int nt = 0; nt < 4; nt++) {
            int cl = wn * 32 + nt * 8 + (lane & 3) * 2;
            int col = bn * 128 + cl;
            float b0 = (col < Nbias) ? bias[col] : 0.f;
            float b1 = (col + 1 < Nbias) ? bias[col + 1] : 0.f;
            float p0 = 0.f, p1 = 0.f;
            #pragma unroll
            for (int mt = 0; mt < 2; mt++)
                #pragma unroll
                for (int h = 0; h < 2; h++) {
                    p0 += fmaxf(acc[mt][nt][2 * h + 0] + b0, 0.f);
                    p1 += fmaxf(acc[mt][nt][2 * h + 1] + b1, 0.f);
                }
            atomicAdd(&sCol[cl], p0);
            atomicAdd(&sCol[cl + 1], p1);
        }
        __syncthreads();
        if (t < 128) part[(size_t)(bm * 8 + bn) * 128 + t] = sCol[t];
    }
}

// ---------------- pool reduce ----------------------------------------------------
__global__ void reduce_pool(float* __restrict__ out) {
    int idx = blockIdx.x * 256 + threadIdx.x;
    if (idx >= BATCH * CLS) return;
    int b = idx / CLS, o = idx % CLS;
    int bn = o >> 7, c = o & 127;
    float s = 0.f;
    #pragma unroll
    for (int q = 0; q < 8; q++)
        s += g_part[(size_t)((b * 8 + q) * 8 + bn) * 128 + c];
    out[idx] = s * (1.0f / 512.0f);
}

// ---------------- launch --------------------------------------------------------
#define DIST_SMEM (64 * 136 * 2 + 128 * 72 * 2)   // 35840 (epilogue) >= 2*DSTG=30720
#define SAGE_SMEM (2 * SSTG)                      // 51200

extern "C" void kernel_launch(void* const* d_in, const int* in_sizes, int n_in,
                              void* d_out, int out_size) {
    const float* x   = (const float*)d_in[0];
    const float* wl0 = (const float*)d_in[1];
    const float* bl0 = (const float*)d_in[2];
    const float* wr0 = (const float*)d_in[3];
    const float* wl1 = (const float*)d_in[4];
    const float* bl1 = (const float*)d_in[5];
    const float* wr1 = (const float*)d_in[6];
    const float* wl2 = (const float*)d_in[7];
    const float* bl2 = (const float*)d_in[8];
    const float* wr2 = (const float*)d_in[9];
    float* out = (float*)d_out;

    f16 *c0h, *c1h, *w0h, *w0l, *w1h, *w1l, *w2h;
    float* part;
    cudaGetSymbolAddress((void**)&c0h, g_c0h);
    cudaGetSymbolAddress((void**)&c1h, g_c1h);
    cudaGetSymbolAddress((void**)&w0h, g_w0h);
    cudaGetSymbolAddress((void**)&w0l, g_w0l);
    cudaGetSymbolAddress((void**)&w1h, g_w1h);
    cudaGetSymbolAddress((void**)&w1l, g_w1l);
    cudaGetSymbolAddress((void**)&w2h, g_w2h);
    cudaGetSymbolAddress((void**)&part, g_part);

    cudaFuncSetAttribute(dist_m64, cudaFuncAttributeMaxDynamicSharedMemorySize, DIST_SMEM);
    cudaFuncSetAttribute(sage_mma<true>, cudaFuncAttributeMaxDynamicSharedMemorySize, SAGE_SMEM);
    cudaFuncSetAttribute(sage_mma<false>, cudaFuncAttributeMaxDynamicSharedMemorySize, SAGE_SMEM);

    sqprep_kernel<<<NN / 8, 256>>>(x);                               // 1
    wt_build01<<<dim3(512, 2), 256>>>(wl0, wr0, wl1, wr1);           // 2
    wt_build2<<<(1024 * 512 + 255) / 256, 256>>>(wl2, wr2);          // 3
    dist_m64<<<4160, 256, DIST_SMEM>>>(c0h + 192);                   // 4 (profiled)
    topk_warp<<<NN / 8, 256>>>(x);                                   // 5

    // layer 0: c0h = [agg(x) | x], K=384 -> h1 (fp16) into c1h self region
    gather_x<<<NN / 4, dim3(FEA / 4, 4)>>>(x, c0h);
    sage_mma<true><<<dim3(2, 128), 256, SAGE_SMEM>>>(c0h, 384, w0h, w0l, bl0, HID,
                                                     c1h + 256, nullptr);
    // layer 1: c1h = [agg(h1) | h1], K=512 -> h2 into c0h self region
    gather_f16<<<NN / 8, dim3(32, 8)>>>(c1h + 256, c1h);
    sage_mma<true><<<dim3(2, 128), 256, SAGE_SMEM>>>(c1h, 512, w1h, w1l, bl1, HID,
                                                     c0h + 256, nullptr);
    // layer 2: c0h = [agg(h2) | h2], K=512, N padded 1024, hi-only weights
    gather_f16<<<NN / 8, dim3(32, 8)>>>(c0h + 256, c0h);
    sage_mma<false><<<dim3(8, 128), 256, SAGE_SMEM>>>(c0h, 512, w2h, nullptr, bl2, CLS,
                                                      nullptr, part);

    reduce_pool<<<(BATCH * CLS + 255) / 256, 256>>>(out);
}

// round 15
// speedup vs baseline: 1.1827x; 1.1827x over previous
#include <cuda_runtime.h>
#include <cuda_fp16.h>
#include <cfloat>

#define NN   8192
#define FEA  192
#define HID  256
#define CLS  1000
#define KNB  9
#define KSTR 512
#define BATCH 16
#define LCAP 128

typedef unsigned int u32;
typedef unsigned short u16;
typedef unsigned long long u64;
typedef __half f16;

// ---------------- scratch ----------------------------------------------------
__device__ float g_sq[NN];
__device__ __half g_Dh[(long long)NN * NN];        // 128 MB approx distances
__device__ __half g_tmin[NN * 64];                 // per-row per-tile minima
__device__ int   g_idx[NN * KNB];
__device__ f16   g_c0h[NN * KSTR];                 // cat buffer 0: [agg | self]
__device__ f16   g_c1h[NN * KSTR];                 // cat buffer 1
__device__ f16   g_w0h[256 * 384],  g_w0l[256 * 384];
__device__ f16   g_w1h[256 * 512];                 // layer1: hi only
__device__ f16   g_w2h[1024 * 512];                // layer2: hi only
__device__ float g_part[1024 * 128];               // layer2 pool partials

// ---------------- helpers ----------------------------------------------------
__device__ __forceinline__ u32 s2u(const void* p) {
    u32 a;
    asm("{.reg .u64 t; cvta.to.shared.u64 t, %1; cvt.u32.u64 %0, t;}" : "=r"(a) : "l"(p));
    return a;
}
__device__ __forceinline__ void cpa16(u32 dst, const void* src) {
    asm volatile("cp.async.cg.shared.global [%0], [%1], 16;" :: "r"(dst), "l"(src));
}
__device__ __forceinline__ void ldsm4(u32* r, u32 addr) {
    asm volatile("ldmatrix.sync.aligned.m8n8.x4.shared.b16 {%0,%1,%2,%3}, [%4];"
        : "=r"(r[0]), "=r"(r[1]), "=r"(r[2]), "=r"(r[3]) : "r"(addr));
}
__device__ __forceinline__ void mma16816(float* c, const u32* a, const u32* b) {
    asm volatile("mma.sync.aligned.m16n8k16.row.col.f32.f16.f16.f32 "
        "{%0,%1,%2,%3},{%4,%5,%6,%7},{%8,%9},{%0,%1,%2,%3};"
        : "+f"(c[0]), "+f"(c[1]), "+f"(c[2]), "+f"(c[3])
        : "r"(a[0]), "r"(a[1]), "r"(a[2]), "r"(a[3]), "r"(b[0]), "r"(b[1]));
}
__device__ __forceinline__ void spltw(float v, f16& h, f16& l) {
    h = __float2half_rn(v);
    l = __float2half_rn(v - __half2float(h));
}
__device__ __forceinline__ u32 okey(u32 hb) {
    return (hb & 0x8000u) ? (hb ^ 0xFFFFu) : (hb | 0x8000u);
}

// fp16 tile loader: [128 rows x 32 k] (row stride 40 halfs = 80B)
__device__ __forceinline__ void ldtile(u32 dstb, const f16* g, int row0, int ld, int k0, int t) {
    #pragma unroll
    for (int q = 0; q < 2; q++) {
        int id = t * 2 + q;
        int row = id >> 2, kq = id & 3;
        cpa16(dstb + row * 80 + kq * 16, g + (size_t)(row0 + row) * ld + k0 + kq * 8);
    }
}
// fp16 tile loader: [64 rows x 32 k]
__device__ __forceinline__ void ldtileA64(u32 dstb, const f16* g, int row0, int ld, int k0, int t) {
    int row = t >> 2, kq = t & 3;
    cpa16(dstb + row * 80 + kq * 16, g + (size_t)(row0 + row) * ld + k0 + kq * 8);
}

#define TB 10240     // 128-row fp16 tile
#define ATB 5120     // 64-row fp16 tile
#define SSTG (ATB + 2 * TB)   // sage stage = 25600

// ---------------- fused sq + fp16 pack -----------------------------------------
__global__ void sqprep_kernel(const float* __restrict__ x) {
    int warp = (blockIdx.x * blockDim.x + threadIdx.x) >> 5;
    int lane = threadIdx.x & 31;
    if (warp >= NN) return;
    const float* r = x + (size_t)warp * FEA;
    float s = 0.f;
    #pragma unroll
    for (int q = 0; q < 2; q++) {
        int c4 = (lane + 32 * q) * 4;
        if (c4 < FEA) {
            float4 v = *(const float4*)(r + c4);
            s += v.x * v.x + v.y * v.y + v.z * v.z + v.w * v.w;
            __half2 p0; p0.x = __float2half_rn(v.x); p0.y = __float2half_rn(v.y);
            __half2 p1; p1.x = __float2half_rn(v.z); p1.y = __float2half_rn(v.w);
            size_t off = (size_t)warp * KSTR + 192 + c4;
            *(__half2*)(g_c0h + off)     = p0;
            *(__half2*)(g_c0h + off + 2) = p1;
        }
    }
    #pragma unroll
    for (int o = 16; o; o >>= 1) s += __shfl_xor_sync(0xffffffffu, s, o);
    if (lane == 0) g_sq[warp] = s;
}

// builds w0 (2-term) and w1 (hi-only)
__global__ void wt_build01(const float* __restrict__ Wl0, const float* __restrict__ Wr0,
                           const float* __restrict__ Wl1, const float* __restrict__ Wr1) {
    int layer = blockIdx.y;
    if (layer == 0) {
        int idx = blockIdx.x * 256 + threadIdx.x;
        if (idx >= 256 * 384) return;
        int k = idx % 384, n = idx / 384;
        float v = (k < 192) ? Wl0[(size_t)k * HID + n] : Wr0[(size_t)(k - 192) * HID + n];
        f16 h, l; spltw(v, h, l);
        g_w0h[idx] = h; g_w0l[idx] = l;
    } else {
        int idx = blockIdx.x * 256 + threadIdx.x;
        if (idx >= 256 * 512) return;
        int k = idx % 512, n = idx / 512;
        float v = (k < 256) ? Wl1[(size_t)k * HID + n] : Wr1[(size_t)(k - 256) * HID + n];
        g_w1h[idx] = __float2half_rn(v);
    }
}

__global__ void wt_build2(const float* __restrict__ Wl, const float* __restrict__ Wr) {
    int idx = blockIdx.x * 256 + threadIdx.x;
    if (idx >= 1024 * 512) return;
    int n = idx / 512, k = idx % 512;
    float v = 0.f;
    if (n < CLS) v = (k < 256) ? Wl[(size_t)k * CLS + n] : Wr[(size_t)(k - 256) * CLS + n];
    g_w2h[idx] = __float2half_rn(v);
}

// ---------------- fp16 distance screen GEMM (triangular grid, M128) ------------
__global__ __launch_bounds__(256, 2) void dist_half(const f16* __restrict__ Xh) {
    int tp = blockIdx.x;
    int bj = (int)((sqrtf(8.f * tp + 1.f) - 1.f) * 0.5f);
    while ((bj + 1) * (bj + 2) / 2 <= tp) bj++;
    while (bj * (bj + 1) / 2 > tp) bj--;
    int bi = tp - bj * (bj + 1) / 2;

    extern __shared__ __align__(16) char smem[];
    u32 sb = s2u(smem);
    int t = threadIdx.x, lane = t & 31, warp = t >> 5;
    int wm = warp & 1, wn = warp >> 1;

    float acc[4][4][4] = {};

    const int NC = FEA / 32;   // 6
    ldtile(sb + 0 * TB, Xh, bi * 128, KSTR, 0, t);
    ldtile(sb + 1 * TB, Xh, bj * 128, KSTR, 0, t);
    asm volatile("cp.async.commit_group;");

    for (int c = 0; c < NC; c++) {
        if (c + 1 < NC) {
            u32 bb = sb + ((c + 1) & 1) * 2 * TB;
            int k0 = (c + 1) * 32;
            ldtile(bb + 0 * TB, Xh, bi * 128, KSTR, k0, t);
            ldtile(bb + 1 * TB, Xh, bj * 128, KSTR, k0, t);
            asm volatile("cp.async.commit_group;");
            asm volatile("cp.async.wait_group 1;");
        } else {
            asm volatile("cp.async.wait_group 0;");
        }
        __syncthreads();
        u32 base = sb + (c & 1) * 2 * TB;
        u32 aH = base, bH = base + TB;
        #pragma unroll
        for (int kk = 0; kk < 32; kk += 16) {
            u32 AH[4][4], BH[4][2];
            #pragma unroll
            for (int mt = 0; mt < 4; mt++) {
                u32 ro = (u32)((wm * 64 + mt * 16 + (lane & 15)) * 80 + (kk + (lane >> 4) * 8) * 2);
                ldsm4(AH[mt], aH + ro);
            }
            #pragma unroll
            for (int np = 0; np < 2; np++) {
                u32 ro = (u32)((wn * 32 + np * 16 + ((lane >> 4) * 8) + (lane & 7)) * 80
                               + (kk + ((lane >> 3) & 1) * 8) * 2);
                u32 r[4];
                ldsm4(r, bH + ro);
                BH[2 * np][0] = r[0]; BH[2 * np][1] = r[1];
                BH[2 * np + 1][0] = r[2]; BH[2 * np + 1][1] = r[3];
            }
            #pragma unroll
            for (int mt = 0; mt < 4; mt++)
                #pragma unroll
                for (int nt = 0; nt < 4; nt++)
                    mma16816(acc[mt][nt], AH[mt], BH[nt]);
        }
        __syncthreads();
    }

    u16* sD = (u16*)smem;            // [128][136]
    u16* sT = sD + 128 * 136;
    bool diag = (bi == bj);
    #pragma unroll
    for (int mt = 0; mt < 4; mt++) {
        int rl0 = wm * 64 + mt * 16 + (lane >> 2);
        #pragma unroll
        for (int nt = 0; nt < 4; nt++) {
            int cl = wn * 32 + nt * 8 + (lane & 3) * 2;
            float sqc0 = g_sq[bj * 128 + cl], sqc1 = g_sq[bj * 128 + cl + 1];
            #pragma unroll
            for (int h = 0; h < 2; h++) {
                int rl = rl0 + h * 8;
                float sr = g_sq[bi * 128 + rl];
                float d0 = sr + sqc0 - 2.f * acc[mt][nt][2 * h + 0];
                float d1 = sr + sqc1 - 2.f * acc[mt][nt][2 * h + 1];
                u16 b0 = __half_as_ushort(__float2half_rn(d0));
                u16 b1 = __half_as_ushort(__float2half_rn(d1));
                sD[rl * 136 + cl] = b0;
                sD[rl * 136 + cl + 1] = b1;
                if (!diag) {
                    sT[cl * 136 + rl] = b0;
                    sT[(cl + 1) * 136 + rl] = b1;
                }
            }
        }
    }
    __syncthreads();
    u16* gD = (u16*)g_Dh;
    for (int e = t; e < 128 * 16; e += 256) {
        int r = e >> 4, c8 = (e & 15) * 8;
        uint4 v = *(uint4*)&sD[r * 136 + c8];
        *(uint4*)(gD + (size_t)(bi * 128 + r) * NN + bj * 128 + c8) = v;
    }
    if (!diag) {
        for (int e = t; e < 128 * 16; e += 256) {
            int r = e >> 4, c8 = (e & 15) * 8;
            uint4 v = *(uint4*)&sT[r * 136 + c8];
            *(uint4*)(gD + (size_t)(bj * 128 + r) * NN + bi * 128 + c8) = v;
        }
    }

    // per-row minima of this tile (2 threads per row)
    {
        int r = t >> 1, hf = t & 1;
        const __half2* pr = (const __half2*)(sD + r * 136 + hf * 64);
        __half2 m2 = pr[0];
        #pragma unroll
        for (int q = 1; q < 32; q++) m2 = __hmin2(m2, pr[q]);
        float fm = fminf(__half2float(__low2half(m2)), __half2float(__high2half(m2)));
        float fo = __shfl_xor_sync(0xffffffffu, fm, 1);
        if (hf == 0)
            g_tmin[(size_t)(bi * 128 + r) * 64 + bj] = __float2half(fminf(fm, fo));
    }
    if (!diag) {
        int r = t >> 1, hf = t & 1;
        const __half2* pr = (const __half2*)(sT + r * 136 + hf * 64);
        __half2 m2 = pr[0];
        #pragma unroll
        for (int q = 1; q < 32; q++) m2 = __hmin2(m2, pr[q]);
        float fm = fminf(__half2float(__low2half(m2)), __half2float(__high2half(m2)));
        float fo = __shfl_xor_sync(0xffffffffu, fm, 1);
        if (hf == 0)
            g_tmin[(size_t)(bj * 128 + r) * 64 + bi] = __float2half(fminf(fm, fo));
    }
}

// ---------------- warp-per-row: tile-min threshold screen + exact refine -------
__global__ __launch_bounds__(256, 6) void topk_warp(const float* __restrict__ x) {
    int lane = threadIdx.x & 31, wid = threadIdx.x >> 5;
    int row = blockIdx.x * 8 + wid;

    __shared__ u32 slist[8][LCAP];
    __shared__ float scd[8][LCAP];
    __shared__ int scnt[8];

    if (lane == 0) scnt[wid] = 0;
    __syncwarp();

    // ---- Phase A: threshold = 16th smallest of the 64 tile mins ----
    const u16* tm = (const u16*)(g_tmin + (size_t)row * 64);
    u32 k0, k1;
    {
        u32 e0 = okey((u32)tm[lane]);
        u32 e1 = okey((u32)tm[lane + 32]);
        k0 = (e0 << 6) | (u32)(lane << 1);
        k1 = (e1 << 6) | (u32)(lane << 1) | 1u;
    }
    u32 m16 = 0;
    #pragma unroll
    for (int r = 0; r < 16; r++) {
        u32 mn = min(k0, k1);
        #pragma unroll
        for (int o = 16; o; o >>= 1) mn = min(mn, __shfl_xor_sync(0xffffffffu, mn, o));
        m16 = mn;
        if (k0 == mn) k0 = 0xFFFFFFFFu;
        else if (k1 == mn) k1 = 0xFFFFFFFFu;
    }
    u32 thr_key = m16 >> 6;
    u32 thr_hb = (thr_key & 0x8000u) ? (thr_key ^ 0x8000u) : (thr_key ^ 0xFFFFu);
    __half2 thr2 = __half2half2(__ushort_as_half((u16)thr_hb));

    // ---- Phase B: filtered stream ----
    const uint4* rp = (const uint4*)(g_Dh + (size_t)row * NN);
    for (int i = 0; i < 32; i++) {
        uint4 v = __ldg(rp + i * 32 + lane);
        union { u32 u; __half2 h; } a0, a1, a2, a3;
        a0.u = v.x; a1.u = v.y; a2.u = v.z; a3.u = v.w;
        __half2 mm = __hmin2(__hmin2(a0.h, a1.h), __hmin2(a2.h, a3.h));
        union { __half2 h; u32 u; } cc; cc.h = __hle2(mm, thr2);
        bool need = (cc.u != 0);
        if (__ballot_sync(0xffffffffu, need)) {
            if (need) {
                u32 w[4] = {v.x, v.y, v.z, v.w};
                u32 base = (u32)((i * 32 + lane) * 8);
                #pragma unroll
                for (int p = 0; p < 4; p++) {
                    #pragma unroll
                    for (int hh = 0; hh < 2; hh++) {
                        u32 key = okey((w[p] >> (16 * hh)) & 0xFFFFu);
                        if (key <= thr_key) {
                            int pos = atomicAdd(&scnt[wid], 1);
                            if (pos < LCAP)
                                slist[wid][pos] = (key << 16) | (base + p * 2 + hh);
                        }
                    }
                }
            }
        }
    }
    __syncwarp();
    int cnt = min(scnt[wid], LCAP);

    // ---- Phase C: exact fp32 refine ----
    float xi[6];
    const float* xr = x + (size_t)row * FEA;
    #pragma unroll
    for (int q = 0; q < 6; q++) xi[q] = __ldg(xr + q * 32 + lane);
    float sqi = g_sq[row];
    for (int c = 0; c < cnt; c++) {
        int j = (int)(slist[wid][c] & 0xFFFFu);
        const float* xj = x + (size_t)j * FEA;
        float s = 0.f;
        #pragma unroll
        for (int q = 0; q < 6; q++) s = fmaf(xi[q], __ldg(xj + q * 32 + lane), s);
        #pragma unroll
        for (int o = 16; o; o >>= 1) s += __shfl_xor_sync(0xffffffffu, s, o);
        if (lane == 0) scd[wid][c] = sqi + g_sq[j] - 2.f * s;
    }
    __syncwarp();

    // ---- Phase D: exact top-9 by (fp32 dist, idx) ----
    u64 mykeys[4];
    #pragma unroll
    for (int q = 0; q < 4; q++) {
        int c = lane + 32 * q;
        if (c < cnt) {
            u32 b = __float_as_uint(scd[wid][c]);
            b ^= (b & 0x80000000u) ? 0xFFFFFFFFu : 0x80000000u;
            mykeys[q] = ((u64)b << 32) | (u32)(slist[wid][c] & 0xFFFFu);
        } else {
            mykeys[q] = ~0ull;
        }
    }
    #pragma unroll
    for (int r = 0; r < KNB; r++) {
        u64 mn = mykeys[0];
        #pragma unroll
        for (int q = 1; q < 4; q++) mn = mykeys[q] < mn ? mykeys[q] : mn;
        #pragma unroll
        for (int o = 16; o; o >>= 1) {
            u64 other = __shfl_xor_sync(0xffffffffu, mn, o);
            mn = other < mn ? other : mn;
        }
        if (lane == 0) g_idx[row * KNB + r] = (int)(mn & 0xFFFFFFFFull);
        #pragma unroll
        for (int q = 0; q < 4; q++) if (mykeys[q] == mn) mykeys[q] = ~0ull;
        __syncwarp();
    }
}

// ---------------- gather + mean from fp32 x (layer 0) --------------------------
__global__ void gather_x(const float* __restrict__ x, f16* __restrict__ oh) {
    int row = blockIdx.x * 4 + threadIdx.y;
    int c4 = threadIdx.x * 4;
    const int* idp = g_idx + row * KNB;
    float4 s = make_float4(0.f, 0.f, 0.f, 0.f);
    #pragma unroll
    for (int j = 0; j < KNB; j++) {
        float4 v = __ldg((const float4*)(x + (size_t)idp[j] * FEA + c4));
        s.x += v.x; s.y += v.y; s.z += v.z; s.w += v.w;
    }
    const float inv = 1.0f / 9.0f;
    size_t off = (size_t)row * KSTR + c4;
    __half2 p0; p0.x = __float2half_rn(s.x * inv); p0.y = __float2half_rn(s.y * inv);
    __half2 p1; p1.x = __float2half_rn(s.z * inv); p1.y = __float2half_rn(s.w * inv);
    *(__half2*)(oh + off)     = p0;
    *(__half2*)(oh + off + 2) = p1;
}

// ---------------- gather + mean from fp16 cat self (layers 1,2) ----------------
__global__ void gather_f16(const f16* __restrict__ cat_self, f16* __restrict__ cat_agg) {
    int row = blockIdx.x * 8 + threadIdx.y;
    int c8 = threadIdx.x * 8;
    const int* idp = g_idx + row * KNB;
    float s[8] = {0.f, 0.f, 0.f, 0.f, 0.f, 0.f, 0.f, 0.f};
    #pragma unroll
    for (int j = 0; j < KNB; j++) {
        uint4 v = __ldg((const uint4*)(cat_self + (size_t)idp[j] * KSTR + c8));
        u32 w[4] = {v.x, v.y, v.z, v.w};
        #pragma unroll
        for (int p = 0; p < 4; p++) {
            float2 f = __half22float2(*(__half2*)&w[p]);
            s[2 * p] += f.x; s[2 * p + 1] += f.y;
        }
    }
    const float inv = 1.0f / 9.0f;
    u32 out[4];
    #pragma unroll
    for (int p = 0; p < 4; p++) {
        __half2 h; h.x = __float2half_rn(s[2 * p] * inv); h.y = __float2half_rn(s[2 * p + 1] * inv);
        out[p] = *(u32*)&h;
    }
    *(uint4*)(cat_agg + (size_t)row * KSTR + c8) = *(uint4*)out;
}

// ---------------- SAGE dual-GEMM, M64 tiles, 3 CTAs/SM --------------------------
template <bool TWOTERM>
__global__ __launch_bounds__(256, 3) void sage_mma(
    const f16* __restrict__ Ah, int Ktot,
    const f16* __restrict__ Bh, const f16* __restrict__ Bl,
    const float* __restrict__ bias, int Nbias,
    f16* __restrict__ Sh, float* __restrict__ part)
{
    int bn = blockIdx.x, bm = blockIdx.y;
    extern __shared__ __align__(16) char smem[];
    u32 sb = s2u(smem);
    int t = threadIdx.x, lane = t & 31, warp = t >> 5;
    int wm = warp & 1, wn = warp >> 1;

    float acc[2][4][4] = {};

    int nc = Ktot / 32;
    ldtileA64(sb + 0, Ah, bm * 64, KSTR, 0, t);
    ldtile(sb + ATB, Bh, bn * 128, Ktot, 0, t);
    if (TWOTERM) ldtile(sb + ATB + TB, Bl, bn * 128, Ktot, 0, t);
    asm volatile("cp.async.commit_group;");

    for (int c = 0; c < nc; c++) {
        if (c + 1 < nc) {
            u32 bb = sb + ((c + 1) & 1) * SSTG;
            int k0 = (c + 1) * 32;
            ldtileA64(bb + 0, Ah, bm * 64, KSTR, k0, t);
            ldtile(bb + ATB, Bh, bn * 128, Ktot, k0, t);
            if (TWOTERM) ldtile(bb + ATB + TB, Bl, bn * 128, Ktot, k0, t);
            asm volatile("cp.async.commit_group;");
            asm volatile("cp.async.wait_group 1;");
        } else {
            asm volatile("cp.async.wait_group 0;");
        }
        __syncthreads();
        u32 base = sb + (c & 1) * SSTG;
        u32 aH = base, bH = base + ATB, bL = base + ATB + TB;
        #pragma unroll
        for (int kk = 0; kk < 32; kk += 16) {
            u32 AH[2][4], BH[4][2], BL[4][2];
            #pragma unroll
            for (int mt = 0; mt < 2; mt++) {
                u32 ro = (u32)((wm * 32 + mt * 16 + (lane & 15)) * 80 + (kk + (lane >> 4) * 8) * 2);
                ldsm4(AH[mt], aH + ro);
            }
            #pragma unroll
            for (int np = 0; np < 2; np++) {
                u32 ro = (u32)((wn * 32 + np * 16 + ((lane >> 4) * 8) + (lane & 7)) * 80
                               + (kk + ((lane >> 3) & 1) * 8) * 2);
                u32 r[4];
                ldsm4(r, bH + ro);
                BH[2 * np][0] = r[0]; BH[2 * np][1] = r[1];
                BH[2 * np + 1][0] = r[2]; BH[2 * np + 1][1] = r[3];
                if (TWOTERM) {
                    ldsm4(r, bL + ro);
                    BL[2 * np][0] = r[0]; BL[2 * np][1] = r[1];
                    BL[2 * np + 1][0] = r[2]; BL[2 * np + 1][1] = r[3];
                }
            }
            #pragma unroll
            for (int mt = 0; mt < 2; mt++)
                #pragma unroll
                for (int nt = 0; nt < 4; nt++) {
                    mma16816(acc[mt][nt], AH[mt], BH[nt]);
                    if (TWOTERM) mma16816(acc[mt][nt], AH[mt], BL[nt]);
                }
        }
        __syncthreads();
    }

    if (Sh) {
        #pragma unroll
        for (int mt = 0; mt < 2; mt++) {
            int rl0 = wm * 32 + mt * 16 + (lane >> 2);
            #pragma unroll
            for (int nt = 0; nt < 4; nt++) {
                int cl = wn * 32 + nt * 8 + (lane & 3) * 2;
                int col = bn * 128 + cl;
                float b0 = bias[col], b1 = bias[col + 1];
                #pragma unroll
                for (int h = 0; h < 2; h++) {
                    int row = bm * 64 + rl0 + h * 8;
                    float v0 = fmaxf(acc[mt][nt][2 * h + 0] + b0, 0.f);
                    float v1 = fmaxf(acc[mt][nt][2 * h + 1] + b1, 0.f);
                    __half2 p; p.x = __float2half_rn(v0); p.y = __float2half_rn(v1);
                    *(__half2*)(Sh + (size_t)row * KSTR + col) = p;
                }
            }
        }
    } else {
        float* sCol = (float*)smem;
        if (t < 128) sCol[t] = 0.f;
        __syncthreads();
        #pragma unroll
        for (int nt = 0; nt < 4; nt++) {
            int cl = wn * 32 + nt * 8 + (lane & 3) * 2;
            int col = bn * 128 + cl;
            float b0 = (col < Nbias) ? bias[col] : 0.f;
            float b1 = (col + 1 < Nbias) ? bias[col + 1] : 0.f;
            float p0 = 0.f, p1 = 0.f;
            #pragma unroll
            for (int mt = 0; mt < 2; mt++)
                #pragma unroll
                for (int h = 0; h < 2; h++) {
                    p0 += fmaxf(acc[mt][nt][2 * h + 0] + b0, 0.f);
                    p1 += fmaxf(acc[mt][nt][2 * h + 1] + b1, 0.f);
                }
            atomicAdd(&sCol[cl], p0);
            atomicAdd(&sCol[cl + 1], p1);
        }
        __syncthreads();
        if (t < 128) part[(size_t)(bm * 8 + bn) * 128 + t] = sCol[t];
    }
}

// ---------------- pool reduce ----------------------------------------------------
__global__ void reduce_pool(float* __restrict__ out) {
    int idx = blockIdx.x * 256 + threadIdx.x;
    if (idx >= BATCH * CLS) return;
    int b = idx / CLS, o = idx % CLS;
    int bn = o >> 7, c = o & 127;
    float s = 0.f;
    #pragma unroll
    for (int q = 0; q < 8; q++)
        s += g_part[(size_t)((b * 8 + q) * 8 + bn) * 128 + c];
    out[idx] = s * (1.0f / 512.0f);
}

// ---------------- launch --------------------------------------------------------
#define DIST_SMEM (128 * 136 * 2 * 2)   // 69632
#define SAGE_SMEM (2 * SSTG)            // 51200

extern "C" void kernel_launch(void* const* d_in, const int* in_sizes, int n_in,
                              void* d_out, int out_size) {
    const float* x   = (const float*)d_in[0];
    const float* wl0 = (const float*)d_in[1];
    const float* bl0 = (const float*)d_in[2];
    const float* wr0 = (const float*)d_in[3];
    const float* wl1 = (const float*)d_in[4];
    const float* bl1 = (const float*)d_in[5];
    const float* wr1 = (const float*)d_in[6];
    const float* wl2 = (const float*)d_in[7];
    const float* bl2 = (const float*)d_in[8];
    const float* wr2 = (const float*)d_in[9];
    float* out = (float*)d_out;

    f16 *c0h, *c1h, *w0h, *w0l, *w1h, *w2h;
    float* part;
    cudaGetSymbolAddress((void**)&c0h, g_c0h);
    cudaGetSymbolAddress((void**)&c1h, g_c1h);
    cudaGetSymbolAddress((void**)&w0h, g_w0h);
    cudaGetSymbolAddress((void**)&w0l, g_w0l);
    cudaGetSymbolAddress((void**)&w1h, g_w1h);
    cudaGetSymbolAddress((void**)&w2h, g_w2h);
    cudaGetSymbolAddress((void**)&part, g_part);

    cudaFuncSetAttribute(dist_half, cudaFuncAttributeMaxDynamicSharedMemorySize, DIST_SMEM);
    cudaFuncSetAttribute(sage_mma<true>, cudaFuncAttributeMaxDynamicSharedMemorySize, SAGE_SMEM);
    cudaFuncSetAttribute(sage_mma<false>, cudaFuncAttributeMaxDynamicSharedMemorySize, SAGE_SMEM);

    sqprep_kernel<<<NN / 8, 256>>>(x);                               // 1
    wt_build01<<<dim3(512, 2), 256>>>(wl0, wr0, wl1, wr1);           // 2
    wt_build2<<<(1024 * 512 + 255) / 256, 256>>>(wl2, wr2);          // 3
    dist_half<<<2080, 256, DIST_SMEM>>>(c0h + 192);                  // 4 (profiled)
    topk_warp<<<NN / 8, 256>>>(x);                                   // 5

    // layer 0: c0h = [agg(x) | x], K=384, 2-term weights
    gather_x<<<NN / 4, dim3(FEA / 4, 4)>>>(x, c0h);
    sage_mma<true><<<dim3(2, 128), 256, SAGE_SMEM>>>(c0h, 384, w0h, w0l, bl0, HID,
                                                     c1h + 256, nullptr);
    // layer 1: c1h = [agg(h1) | h1], K=512, hi-only weights
    gather_f16<<<NN / 8, dim3(32, 8)>>>(c1h + 256, c1h);
    sage_mma<false><<<dim3(2, 128), 256, SAGE_SMEM>>>(c1h, 512, w1h, nullptr, bl1, HID,
                                                      c0h + 256, nullptr);
    // layer 2: c0h = [agg(h2) | h2], K=512, N padded 1024, hi-only weights
    gather_f16<<<NN / 8, dim3(32, 8)>>>(c0h + 256, c0h);
    sage_mma<false><<<dim3(8, 128), 256, SAGE_SMEM>>>(c0h, 512, w2h, nullptr, bl2, CLS,
                                                      nullptr, part);

    reduce_pool<<<(BATCH * CLS + 255) / 256, 256>>>(out);
}

// round 16
// speedup vs baseline: 1.2214x; 1.0327x over previous
#include <cuda_runtime.h>
#include <cuda_fp16.h>
#include <cfloat>

#define NN   8192
#define FEA  192
#define HID  256
#define CLS  1000
#define KNB  9
#define KSTR 512
#define BATCH 16
#define LCAP 128

typedef unsigned int u32;
typedef unsigned short u16;
typedef unsigned long long u64;
typedef __half f16;

// ---------------- scratch ----------------------------------------------------
__device__ float g_sq[NN];
__device__ __half g_Dh[(long long)NN * NN];        // 128 MB approx distances
__device__ __half g_tmin[NN * 64];                 // per-row per-tile minima
__device__ int   g_idx[NN * KNB];
__device__ f16   g_c0h[NN * KSTR];                 // cat buffer 0: [agg | self]
__device__ f16   g_c1h[NN * KSTR];                 // cat buffer 1
__device__ f16   g_w0h[256 * 384],  g_w0l[256 * 384];
__device__ f16   g_w1h[256 * 512];                 // layer1: hi only
__device__ f16   g_w2h[1024 * 512];                // layer2: hi only
__device__ float g_part[1024 * 128];               // layer2 pool partials

// ---------------- helpers ----------------------------------------------------
__device__ __forceinline__ u32 s2u(const void* p) {
    u32 a;
    asm("{.reg .u64 t; cvta.to.shared.u64 t, %1; cvt.u32.u64 %0, t;}" : "=r"(a) : "l"(p));
    return a;
}
__device__ __forceinline__ void cpa16(u32 dst, const void* src) {
    asm volatile("cp.async.cg.shared.global [%0], [%1], 16;" :: "r"(dst), "l"(src));
}
__device__ __forceinline__ void ldsm4(u32* r, u32 addr) {
    asm volatile("ldmatrix.sync.aligned.m8n8.x4.shared.b16 {%0,%1,%2,%3}, [%4];"
        : "=r"(r[0]), "=r"(r[1]), "=r"(r[2]), "=r"(r[3]) : "r"(addr));
}
__device__ __forceinline__ void mma16816(float* c, const u32* a, const u32* b) {
    asm volatile("mma.sync.aligned.m16n8k16.row.col.f32.f16.f16.f32 "
        "{%0,%1,%2,%3},{%4,%5,%6,%7},{%8,%9},{%0,%1,%2,%3};"
        : "+f"(c[0]), "+f"(c[1]), "+f"(c[2]), "+f"(c[3])
        : "r"(a[0]), "r"(a[1]), "r"(a[2]), "r"(a[3]), "r"(b[0]), "r"(b[1]));
}
__device__ __forceinline__ void spltw(float v, f16& h, f16& l) {
    h = __float2half_rn(v);
    l = __float2half_rn(v - __half2float(h));
}
__device__ __forceinline__ u32 okey(u32 hb) {
    return (hb & 0x8000u) ? (hb ^ 0xFFFFu) : (hb | 0x8000u);
}

// fp16 tile loader: [128 rows x 32 k] (row stride 40 halfs = 80B)
__device__ __forceinline__ void ldtile(u32 dstb, const f16* g, int row0, int ld, int k0, int t) {
    #pragma unroll
    for (int q = 0; q < 2; q++) {
        int id = t * 2 + q;
        int row = id >> 2, kq = id & 3;
        cpa16(dstb + row * 80 + kq * 16, g + (size_t)(row0 + row) * ld + k0 + kq * 8);
    }
}
// fp16 tile loader: [64 rows x 32 k]
__device__ __forceinline__ void ldtileA64(u32 dstb, const f16* g, int row0, int ld, int k0, int t) {
    int row = t >> 2, kq = t & 3;
    cpa16(dstb + row * 80 + kq * 16, g + (size_t)(row0 + row) * ld + k0 + kq * 8);
}

#define TB 10240     // 128-row fp16 tile
#define ATB 5120     // 64-row fp16 tile
#define SSTG (ATB + 2 * TB)   // sage stage = 25600

// ---------------- fused sq + fp16 pack -----------------------------------------
__global__ void sqprep_kernel(const float* __restrict__ x) {
    int warp = (blockIdx.x * blockDim.x + threadIdx.x) >> 5;
    int lane = threadIdx.x & 31;
    if (warp >= NN) return;
    const float* r = x + (size_t)warp * FEA;
    float s = 0.f;
    #pragma unroll
    for (int q = 0; q < 2; q++) {
        int c4 = (lane + 32 * q) * 4;
        if (c4 < FEA) {
            float4 v = *(const float4*)(r + c4);
            s += v.x * v.x + v.y * v.y + v.z * v.z + v.w * v.w;
            __half2 p0; p0.x = __float2half_rn(v.x); p0.y = __float2half_rn(v.y);
            __half2 p1; p1.x = __float2half_rn(v.z); p1.y = __float2half_rn(v.w);
            size_t off = (size_t)warp * KSTR + 192 + c4;
            *(__half2*)(g_c0h + off)     = p0;
            *(__half2*)(g_c0h + off + 2) = p1;
        }
    }
    #pragma unroll
    for (int o = 16; o; o >>= 1) s += __shfl_xor_sync(0xffffffffu, s, o);
    if (lane == 0) g_sq[warp] = s;
}

// all weight builds in one launch
__global__ void wt_build_all(const float* __restrict__ Wl0, const float* __restrict__ Wr0,
                             const float* __restrict__ Wl1, const float* __restrict__ Wr1,
                             const float* __restrict__ Wl2, const float* __restrict__ Wr2) {
    int layer = blockIdx.y;
    int idx = blockIdx.x * 256 + threadIdx.x;
    if (layer == 0) {
        if (idx >= 256 * 384) return;
        int k = idx % 384, n = idx / 384;
        float v = (k < 192) ? Wl0[(size_t)k * HID + n] : Wr0[(size_t)(k - 192) * HID + n];
        f16 h, l; spltw(v, h, l);
        g_w0h[idx] = h; g_w0l[idx] = l;
    } else if (layer == 1) {
        if (idx >= 256 * 512) return;
        int k = idx % 512, n = idx / 512;
        float v = (k < 256) ? Wl1[(size_t)k * HID + n] : Wr1[(size_t)(k - 256) * HID + n];
        g_w1h[idx] = __float2half_rn(v);
    } else {
        if (idx >= 1024 * 512) return;
        int n = idx / 512, k = idx % 512;
        float v = 0.f;
        if (n < CLS) v = (k < 256) ? Wl2[(size_t)k * CLS + n] : Wr2[(size_t)(k - 256) * CLS + n];
        g_w2h[idx] = __float2half_rn(v);
    }
}

// ---------------- fp16 distance screen GEMM (triangular grid, M128) ------------
__global__ __launch_bounds__(256, 2) void dist_half(const f16* __restrict__ Xh) {
    int tp = blockIdx.x;
    int bj = (int)((sqrtf(8.f * tp + 1.f) - 1.f) * 0.5f);
    while ((bj + 1) * (bj + 2) / 2 <= tp) bj++;
    while (bj * (bj + 1) / 2 > tp) bj--;
    int bi = tp - bj * (bj + 1) / 2;

    extern __shared__ __align__(16) char smem[];
    u32 sb = s2u(smem);
    int t = threadIdx.x, lane = t & 31, warp = t >> 5;
    int wm = warp & 1, wn = warp >> 1;

    float acc[4][4][4] = {};

    const int NC = FEA / 32;   // 6
    ldtile(sb + 0 * TB, Xh, bi * 128, KSTR, 0, t);
    ldtile(sb + 1 * TB, Xh, bj * 128, KSTR, 0, t);
    asm volatile("cp.async.commit_group;");

    for (int c = 0; c < NC; c++) {
        if (c + 1 < NC) {
            u32 bb = sb + ((c + 1) & 1) * 2 * TB;
            int k0 = (c + 1) * 32;
            ldtile(bb + 0 * TB, Xh, bi * 128, KSTR, k0, t);
            ldtile(bb + 1 * TB, Xh, bj * 128, KSTR, k0, t);
            asm volatile("cp.async.commit_group;");
            asm volatile("cp.async.wait_group 1;");
        } else {
            asm volatile("cp.async.wait_group 0;");
        }
        __syncthreads();
        u32 base = sb + (c & 1) * 2 * TB;
        u32 aH = base, bH = base + TB;
        #pragma unroll
        for (int kk = 0; kk < 32; kk += 16) {
            u32 AH[4][4], BH[4][2];
            #pragma unroll
            for (int mt = 0; mt < 4; mt++) {
                u32 ro = (u32)((wm * 64 + mt * 16 + (lane & 15)) * 80 + (kk + (lane >> 4) * 8) * 2);
                ldsm4(AH[mt], aH + ro);
            }
            #pragma unroll
            for (int np = 0; np < 2; np++) {
                u32 ro = (u32)((wn * 32 + np * 16 + ((lane >> 4) * 8) + (lane & 7)) * 80
                               + (kk + ((lane >> 3) & 1) * 8) * 2);
                u32 r[4];
                ldsm4(r, bH + ro);
                BH[2 * np][0] = r[0]; BH[2 * np][1] = r[1];
                BH[2 * np + 1][0] = r[2]; BH[2 * np + 1][1] = r[3];
            }
            #pragma unroll
            for (int mt = 0; mt < 4; mt++)
                #pragma unroll
                for (int nt = 0; nt < 4; nt++)
                    mma16816(acc[mt][nt], AH[mt], BH[nt]);
        }
        __syncthreads();
    }

    u16* sD = (u16*)smem;            // [128][136]
    u16* sT = sD + 128 * 136;
    bool diag = (bi == bj);
    #pragma unroll
    for (int mt = 0; mt < 4; mt++) {
        int rl0 = wm * 64 + mt * 16 + (lane >> 2);
        #pragma unroll
        for (int nt = 0; nt < 4; nt++) {
            int cl = wn * 32 + nt * 8 + (lane & 3) * 2;
            float sqc0 = g_sq[bj * 128 + cl], sqc1 = g_sq[bj * 128 + cl + 1];
            #pragma unroll
            for (int h = 0; h < 2; h++) {
                int rl = rl0 + h * 8;
                float sr = g_sq[bi * 128 + rl];
                float d0 = sr + sqc0 - 2.f * acc[mt][nt][2 * h + 0];
                float d1 = sr + sqc1 - 2.f * acc[mt][nt][2 * h + 1];
                u16 b0 = __half_as_ushort(__float2half_rn(d0));
                u16 b1 = __half_as_ushort(__float2half_rn(d1));
                sD[rl * 136 + cl] = b0;
                sD[rl * 136 + cl + 1] = b1;
                if (!diag) {
                    sT[cl * 136 + rl] = b0;
                    sT[(cl + 1) * 136 + rl] = b1;
                }
            }
        }
    }
    __syncthreads();
    u16* gD = (u16*)g_Dh;
    for (int e = t; e < 128 * 16; e += 256) {
        int r = e >> 4, c8 = (e & 15) * 8;
        uint4 v = *(uint4*)&sD[r * 136 + c8];
        *(uint4*)(gD + (size_t)(bi * 128 + r) * NN + bj * 128 + c8) = v;
    }
    if (!diag) {
        for (int e = t; e < 128 * 16; e += 256) {
            int r = e >> 4, c8 = (e & 15) * 8;
            uint4 v = *(uint4*)&sT[r * 136 + c8];
            *(uint4*)(gD + (size_t)(bj * 128 + r) * NN + bi * 128 + c8) = v;
        }
    }

    {
        int r = t >> 1, hf = t & 1;
        const __half2* pr = (const __half2*)(sD + r * 136 + hf * 64);
        __half2 m2 = pr[0];
        #pragma unroll
        for (int q = 1; q < 32; q++) m2 = __hmin2(m2, pr[q]);
        float fm = fminf(__half2float(__low2half(m2)), __half2float(__high2half(m2)));
        float fo = __shfl_xor_sync(0xffffffffu, fm, 1);
        if (hf == 0)
            g_tmin[(size_t)(bi * 128 + r) * 64 + bj] = __float2half(fminf(fm, fo));
    }
    if (!diag) {
        int r = t >> 1, hf = t & 1;
        const __half2* pr = (const __half2*)(sT + r * 136 + hf * 64);
        __half2 m2 = pr[0];
        #pragma unroll
        for (int q = 1; q < 32; q++) m2 = __hmin2(m2, pr[q]);
        float fm = fminf(__half2float(__low2half(m2)), __half2float(__high2half(m2)));
        float fo = __shfl_xor_sync(0xffffffffu, fm, 1);
        if (hf == 0)
            g_tmin[(size_t)(bj * 128 + r) * 64 + bi] = __float2half(fminf(fm, fo));
    }
}

// ---------------- warp-per-row: tile-skip screen + exact refine -----------------
__global__ __launch_bounds__(256, 6) void topk_warp(const float* __restrict__ x) {
    int lane = threadIdx.x & 31, wid = threadIdx.x >> 5;
    int row = blockIdx.x * 8 + wid;

    __shared__ u32 slist[8][LCAP];
    __shared__ float scd[8][LCAP];
    __shared__ u16 stkey[8][64];
    __shared__ int scnt[8];

    if (lane == 0) scnt[wid] = 0;
    __syncwarp();

    // ---- Phase A: tile keys + threshold = 16th smallest of 64 tile mins ----
    const u16* tm = (const u16*)(g_tmin + (size_t)row * 64);
    u32 e0 = okey((u32)tm[lane]);
    u32 e1 = okey((u32)tm[lane + 32]);
    stkey[wid][lane]      = (u16)e0;
    stkey[wid][lane + 32] = (u16)e1;
    u32 k0 = (e0 << 6) | (u32)(lane << 1);
    u32 k1 = (e1 << 6) | (u32)(lane << 1) | 1u;
    u32 m16 = 0;
    #pragma unroll
    for (int r = 0; r < 16; r++) {
        u32 mn = min(k0, k1);
        #pragma unroll
        for (int o = 16; o; o >>= 1) mn = min(mn, __shfl_xor_sync(0xffffffffu, mn, o));
        m16 = mn;
        if (k0 == mn) k0 = 0xFFFFFFFFu;
        else if (k1 == mn) k1 = 0xFFFFFFFFu;
    }
    u32 thr_key = m16 >> 6;
    u32 thr_hb = (thr_key & 0x8000u) ? (thr_key ^ 0x8000u) : (thr_key ^ 0xFFFFu);
    __half2 thr2 = __half2half2(__ushort_as_half((u16)thr_hb));
    __syncwarp();

    // ---- Phase B: tile-skipping filtered stream ----
    const uint4* rp = (const uint4*)(g_Dh + (size_t)row * NN);
    for (int i = 0; i < 32; i++) {
        int tl = (i * 32 + lane) >> 4;
        bool active = ((u32)stkey[wid][tl] <= thr_key);
        bool need = false;
        uint4 v = make_uint4(0, 0, 0, 0);
        if (active) {
            v = __ldg(rp + i * 32 + lane);
            union { u32 u; __half2 h; } a0, a1, a2, a3;
            a0.u = v.x; a1.u = v.y; a2.u = v.z; a3.u = v.w;
            __half2 mm = __hmin2(__hmin2(a0.h, a1.h), __hmin2(a2.h, a3.h));
            union { __half2 h; u32 u; } cc; cc.h = __hle2(mm, thr2);
            need = (cc.u != 0);
        }
        if (__ballot_sync(0xffffffffu, need)) {
            if (need) {
                u32 w[4] = {v.x, v.y, v.z, v.w};
                u32 base = (u32)((i * 32 + lane) * 8);
                #pragma unroll
                for (int p = 0; p < 4; p++) {
                    #pragma unroll
                    for (int hh = 0; hh < 2; hh++) {
                        u32 key = okey((w[p] >> (16 * hh)) & 0xFFFFu);
                        if (key <= thr_key) {
                            int pos = atomicAdd(&scnt[wid], 1);
                            if (pos < LCAP)
                                slist[wid][pos] = (key << 16) | (base + p * 2 + hh);
                        }
                    }
                }
            }
        }
    }
    __syncwarp();
    int cnt = min(scnt[wid], LCAP);

    // ---- Phase C: exact fp32 refine ----
    float xi[6];
    const float* xr = x + (size_t)row * FEA;
    #pragma unroll
    for (int q = 0; q < 6; q++) xi[q] = __ldg(xr + q * 32 + lane);
    float sqi = g_sq[row];
    for (int c = 0; c < cnt; c++) {
        int j = (int)(slist[wid][c] & 0xFFFFu);
        const float* xj = x + (size_t)j * FEA;
        float s = 0.f;
        #pragma unroll
        for (int q = 0; q < 6; q++) s = fmaf(xi[q], __ldg(xj + q * 32 + lane), s);
        #pragma unroll
        for (int o = 16; o; o >>= 1) s += __shfl_xor_sync(0xffffffffu, s, o);
        if (lane == 0) scd[wid][c] = sqi + g_sq[j] - 2.f * s;
    }
    __syncwarp();

    // ---- Phase D: exact top-9 by (fp32 dist, idx) ----
    u64 mykeys[4];
    #pragma unroll
    for (int q = 0; q < 4; q++) {
        int c = lane + 32 * q;
        if (c < cnt) {
            u32 b = __float_as_uint(scd[wid][c]);
            b ^= (b & 0x80000000u) ? 0xFFFFFFFFu : 0x80000000u;
            mykeys[q] = ((u64)b << 32) | (u32)(slist[wid][c] & 0xFFFFu);
        } else {
            mykeys[q] = ~0ull;
        }
    }
    #pragma unroll
    for (int r = 0; r < KNB; r++) {
        u64 mn = mykeys[0];
        #pragma unroll
        for (int q = 1; q < 4; q++) mn = mykeys[q] < mn ? mykeys[q] : mn;
        #pragma unroll
        for (int o = 16; o; o >>= 1) {
            u64 other = __shfl_xor_sync(0xffffffffu, mn, o);
            mn = other < mn ? other : mn;
        }
        if (lane == 0) g_idx[row * KNB + r] = (int)(mn & 0xFFFFFFFFull);
        #pragma unroll
        for (int q = 0; q < 4; q++) if (mykeys[q] == mn) mykeys[q] = ~0ull;
        __syncwarp();
    }
}

// ---------------- gather + mean from fp32 x (layer 0) --------------------------
__global__ void gather_x(const float* __restrict__ x, f16* __restrict__ oh) {
    int row = blockIdx.x * 4 + threadIdx.y;
    int c4 = threadIdx.x * 4;
    const int* idp = g_idx + row * KNB;
    float4 s = make_float4(0.f, 0.f, 0.f, 0.f);
    #pragma unroll
    for (int j = 0; j < KNB; j++) {
        float4 v = __ldg((const float4*)(x + (size_t)idp[j] * FEA + c4));
        s.x += v.x; s.y += v.y; s.z += v.z; s.w += v.w;
    }
    const float inv = 1.0f / 9.0f;
    size_t off = (size_t)row * KSTR + c4;
    __half2 p0; p0.x = __float2half_rn(s.x * inv); p0.y = __float2half_rn(s.y * inv);
    __half2 p1; p1.x = __float2half_rn(s.z * inv); p1.y = __float2half_rn(s.w * inv);
    *(__half2*)(oh + off)     = p0;
    *(__half2*)(oh + off + 2) = p1;
}

// ---------------- gather + mean from fp16 cat self (layers 1,2) ----------------
__global__ void gather_f16(const f16* __restrict__ cat_self, f16* __restrict__ cat_agg) {
    int row = blockIdx.x * 8 + threadIdx.y;
    int c8 = threadIdx.x * 8;
    const int* idp = g_idx + row * KNB;
    float s[8] = {0.f, 0.f, 0.f, 0.f, 0.f, 0.f, 0.f, 0.f};
    #pragma unroll
    for (int j = 0; j < KNB; j++) {
        uint4 v = __ldg((const uint4*)(cat_self + (size_t)idp[j] * KSTR + c8));
        u32 w[4] = {v.x, v.y, v.z, v.w};
        #pragma unroll
        for (int p = 0; p < 4; p++) {
            float2 f = __half22float2(*(__half2*)&w[p]);
            s[2 * p] += f.x; s[2 * p + 1] += f.y;
        }
    }
    const float inv = 1.0f / 9.0f;
    u32 out[4];
    #pragma unroll
    for (int p = 0; p < 4; p++) {
        __half2 h; h.x = __float2half_rn(s[2 * p] * inv); h.y = __float2half_rn(s[2 * p + 1] * inv);
        out[p] = *(u32*)&h;
    }
    *(uint4*)(cat_agg + (size_t)row * KSTR + c8) = *(uint4*)out;
}

// ---------------- SAGE dual-GEMM, M64 tiles, 3 CTAs/SM --------------------------
template <bool TWOTERM>
__global__ __launch_bounds__(256, 3) void sage_mma(
    const f16* __restrict__ Ah, int Ktot,
    const f16* __restrict__ Bh, const f16* __restrict__ Bl,
    const float* __restrict__ bias, int Nbias,
    f16* __restrict__ Sh, float* __restrict__ part)
{
    int bn = blockIdx.x, bm = blockIdx.y;
    extern __shared__ __align__(16) char smem[];
    u32 sb = s2u(smem);
    int t = threadIdx.x, lane = t & 31, warp = t >> 5;
    int wm = warp & 1, wn = warp >> 1;

    float acc[2][4][4] = {};

    int nc = Ktot / 32;
    ldtileA64(sb + 0, Ah, bm * 64, KSTR, 0, t);
    ldtile(sb + ATB, Bh, bn * 128, Ktot, 0, t);
    if (TWOTERM) ldtile(sb + ATB + TB, Bl, bn * 128, Ktot, 0, t);
    asm volatile("cp.async.commit_group;");

    for (int c = 0; c < nc; c++) {
        if (c + 1 < nc) {
            u32 bb = sb + ((c + 1) & 1) * SSTG;
            int k0 = (c + 1) * 32;
            ldtileA64(bb + 0, Ah, bm * 64, KSTR, k0, t);
            ldtile(bb + ATB, Bh, bn * 128, Ktot, k0, t);
            if (TWOTERM) ldtile(bb + ATB + TB, Bl, bn * 128, Ktot, k0, t);
            asm volatile("cp.async.commit_group;");
            asm volatile("cp.async.wait_group 1;");
        } else {
            asm volatile("cp.async.wait_group 0;");
        }
        __syncthreads();
        u32 base = sb + (c & 1) * SSTG;
        u32 aH = base, bH = base + ATB, bL = base + ATB + TB;
        #pragma unroll
        for (int kk = 0; kk < 32; kk += 16) {
            u32 AH[2][4], BH[4][2], BL[4][2];
            #pragma unroll
            for (int mt = 0; mt < 2; mt++) {
                u32 ro = (u32)((wm * 32 + mt * 16 + (lane & 15)) * 80 + (kk + (lane >> 4) * 8) * 2);
                ldsm4(AH[mt], aH + ro);
            }
            #pragma unroll
            for (int np = 0; np < 2; np++) {
                u32 ro = (u32)((wn * 32 + np * 16 + ((lane >> 4) * 8) + (lane & 7)) * 80
                               + (kk + ((lane >> 3) & 1) * 8) * 2);
                u32 r[4];
                ldsm4(r, bH + ro);
                BH[2 * np][0] = r[0]; BH[2 * np][1] = r[1];
                BH[2 * np + 1][0] = r[2]; BH[2 * np + 1][1] = r[3];
                if (TWOTERM) {
                    ldsm4(r, bL + ro);
                    BL[2 * np][0] = r[0]; BL[2 * np][1] = r[1];
                    BL[2 * np + 1][0] = r[2]; BL[2 * np + 1][1] = r[3];
                }
            }
            #pragma unroll
            for (int mt = 0; mt < 2; mt++)
                #pragma unroll
                for (int nt = 0; nt < 4; nt++) {
                    mma16816(acc[mt][nt], AH[mt], BH[nt]);
                    if (TWOTERM) mma16816(acc[mt][nt], AH[mt], BL[nt]);
                }
        }
        __syncthreads();
    }

    if (Sh) {
        #pragma unroll
        for (int mt = 0; mt < 2; mt++) {
            int rl0 = wm * 32 + mt * 16 + (lane >> 2);
            #pragma unroll
            for (int nt = 0; nt < 4; nt++) {
                int cl = wn * 32 + nt * 8 + (lane & 3) * 2;
                int col = bn * 128 + cl;
                float b0 = bias[col], b1 = bias[col + 1];
                #pragma unroll
                for (int h = 0; h < 2; h++) {
                    int row = bm * 64 + rl0 + h * 8;
                    float v0 = fmaxf(acc[mt][nt][2 * h + 0] + b0, 0.f);
                    float v1 = fmaxf(acc[mt][nt][2 * h + 1] + b1, 0.f);
                    __half2 p; p.x = __float2half_rn(v0); p.y = __float2half_rn(v1);
                    *(__half2*)(Sh + (size_t)row * KSTR + col) = p;
                }
            }
        }
    } else {
        float* sCol = (float*)smem;
        if (t < 128) sCol[t] = 0.f;
        __syncthreads();
        #pragma unroll
        for (int nt = 0; nt < 4; nt++) {
            int cl = wn * 32 + nt * 8 + (lane & 3) * 2;
            int col = bn * 128 + cl;
            float b0 = (col < Nbias) ? bias[col] : 0.f;
            float b1 = (col + 1 < Nbias) ? bias[col + 1] : 0.f;
            float p0 = 0.f, p1 = 0.f;
            #pragma unroll
            for (int mt = 0; mt < 2; mt++)
                #pragma unroll
                for (int h = 0; h < 2; h++) {
                    p0 += fmaxf(acc[mt][nt][2 * h + 0] + b0, 0.f);
                    p1 += fmaxf(acc[mt][nt][2 * h + 1] + b1, 0.f);
                }
            atomicAdd(&sCol[cl], p0);
            atomicAdd(&sCol[cl + 1], p1);
        }
        __syncthreads();
        if (t < 128) part[(size_t)(bm * 8 + bn) * 128 + t] = sCol[t];
    }
}

// ---------------- pool reduce ----------------------------------------------------
__global__ void reduce_pool(float* __restrict__ out) {
    int idx = blockIdx.x * 256 + threadIdx.x;
    if (idx >= BATCH * CLS) return;
    int b = idx / CLS, o = idx % CLS;
    int bn = o >> 7, c = o & 127;
    float s = 0.f;
    #pragma unroll
    for (int q = 0; q < 8; q++)
        s += g_part[(size_t)((b * 8 + q) * 8 + bn) * 128 + c];
    out[idx] = s * (1.0f / 512.0f);
}

// ---------------- launch --------------------------------------------------------
#define DIST_SMEM (128 * 136 * 2 * 2)   // 69632
#define SAGE_SMEM (2 * SSTG)            // 51200

extern "C" void kernel_launch(void* const* d_in, const int* in_sizes, int n_in,
                              void* d_out, int out_size) {
    const float* x   = (const float*)d_in[0];
    const float* wl0 = (const float*)d_in[1];
    const float* bl0 = (const float*)d_in[2];
    const float* wr0 = (const float*)d_in[3];
    const float* wl1 = (const float*)d_in[4];
    const float* bl1 = (const float*)d_in[5];
    const float* wr1 = (const float*)d_in[6];
    const float* wl2 = (const float*)d_in[7];
    const float* bl2 = (const float*)d_in[8];
    const float* wr2 = (const float*)d_in[9];
    float* out = (float*)d_out;

    f16 *c0h, *c1h, *w0h, *w0l, *w1h, *w2h;
    float* part;
    cudaGetSymbolAddress((void**)&c0h, g_c0h);
    cudaGetSymbolAddress((void**)&c1h, g_c1h);
    cudaGetSymbolAddress((void**)&w0h, g_w0h);
    cudaGetSymbolAddress((void**)&w0l, g_w0l);
    cudaGetSymbolAddress((void**)&w1h, g_w1h);
    cudaGetSymbolAddress((void**)&w2h, g_w2h);
    cudaGetSymbolAddress((void**)&part, g_part);

    cudaFuncSetAttribute(dist_half, cudaFuncAttributeMaxDynamicSharedMemorySize, DIST_SMEM);
    cudaFuncSetAttribute(sage_mma<true>, cudaFuncAttributeMaxDynamicSharedMemorySize, SAGE_SMEM);
    cudaFuncSetAttribute(sage_mma<false>, cudaFuncAttributeMaxDynamicSharedMemorySize, SAGE_SMEM);

    sqprep_kernel<<<NN / 8, 256>>>(x);                                  // 1
    wt_build_all<<<dim3(2048, 3), 256>>>(wl0, wr0, wl1, wr1, wl2, wr2); // 2
    dist_half<<<2080, 256, DIST_SMEM>>>(c0h + 192);                     // 3
    topk_warp<<<NN / 8, 256>>>(x);                                      // 4 (profiled)

    // layer 0: c0h = [agg(x) | x], K=384, 2-term weights
    gather_x<<<NN / 4, dim3(FEA / 4, 4)>>>(x, c0h);
    sage_mma<true><<<dim3(2, 128), 256, SAGE_SMEM>>>(c0h, 384, w0h, w0l, bl0, HID,
                                                     c1h + 256, nullptr);
    // layer 1: c1h = [agg(h1) | h1], K=512, hi-only weights
    gather_f16<<<NN / 8, dim3(32, 8)>>>(c1h + 256, c1h);
    sage_mma<false><<<dim3(2, 128), 256, SAGE_SMEM>>>(c1h, 512, w1h, nullptr, bl1, HID,
                                                      c0h + 256, nullptr);
    // layer 2: c0h = [agg(h2) | h2], K=512, N padded 1024, hi-only weights
    gather_f16<<<NN / 8, dim3(32, 8)>>>(c0h + 256, c0h);
    sage_mma<false><<<dim3(8, 128), 256, SAGE_SMEM>>>(c0h, 512, w2h, nullptr, bl2, CLS,
                                                      nullptr, part);

    reduce_pool<<<(BATCH * CLS + 255) / 256, 256>>>(out);
}

// round 17
// speedup vs baseline: 1.2796x; 1.0476x over previous
#include <cuda_runtime.h>
#include <cuda_fp16.h>
#include <cfloat>

#define NN   8192
#define FEA  192
#define HID  256
#define CLS  1000
#define KNB  9
#define KSTR 512
#define BATCH 16
#define LCAP 128

typedef unsigned int u32;
typedef unsigned short u16;
typedef unsigned long long u64;
typedef __half f16;

// ---------------- scratch ----------------------------------------------------
__device__ float g_sq[NN];
__device__ __half g_Dh[(long long)NN * NN];        // 128 MB approx distances
__device__ __half g_tmin[NN * 64];                 // per-row per-tile minima
__device__ int   g_idx[NN * KNB];
__device__ f16   g_c0h[NN * KSTR];                 // cat buffer 0: [agg | self]
__device__ f16   g_c1h[NN * KSTR];                 // cat buffer 1
__device__ f16   g_w0h[256 * 384],  g_w0l[256 * 384];
__device__ f16   g_w1h[256 * 512];                 // layer1: hi only
__device__ f16   g_w2h[1024 * 512];                // layer2: hi only
__device__ float g_part[1024 * 128];               // layer2 pool partials

// ---------------- helpers ----------------------------------------------------
__device__ __forceinline__ u32 s2u(const void* p) {
    u32 a;
    asm("{.reg .u64 t; cvta.to.shared.u64 t, %1; cvt.u32.u64 %0, t;}" : "=r"(a) : "l"(p));
    return a;
}
__device__ __forceinline__ void cpa16(u32 dst, const void* src) {
    asm volatile("cp.async.cg.shared.global [%0], [%1], 16;" :: "r"(dst), "l"(src));
}
__device__ __forceinline__ void ldsm4(u32* r, u32 addr) {
    asm volatile("ldmatrix.sync.aligned.m8n8.x4.shared.b16 {%0,%1,%2,%3}, [%4];"
        : "=r"(r[0]), "=r"(r[1]), "=r"(r[2]), "=r"(r[3]) : "r"(addr));
}
__device__ __forceinline__ void mma16816(float* c, const u32* a, const u32* b) {
    asm volatile("mma.sync.aligned.m16n8k16.row.col.f32.f16.f16.f32 "
        "{%0,%1,%2,%3},{%4,%5,%6,%7},{%8,%9},{%0,%1,%2,%3};"
        : "+f"(c[0]), "+f"(c[1]), "+f"(c[2]), "+f"(c[3])
        : "r"(a[0]), "r"(a[1]), "r"(a[2]), "r"(a[3]), "r"(b[0]), "r"(b[1]));
}
__device__ __forceinline__ void spltw(float v, f16& h, f16& l) {
    h = __float2half_rn(v);
    l = __float2half_rn(v - __half2float(h));
}
__device__ __forceinline__ u32 okey(u32 hb) {
    return (hb & 0x8000u) ? (hb ^ 0xFFFFu) : (hb | 0x8000u);
}

// fp16 tile loader: [128 rows x 32 k] (row stride 40 halfs = 80B)
__device__ __forceinline__ void ldtile(u32 dstb, const f16* g, int row0, int ld, int k0, int t) {
    #pragma unroll
    for (int q = 0; q < 2; q++) {
        int id = t * 2 + q;
        int row = id >> 2, kq = id & 3;
        cpa16(dstb + row * 80 + kq * 16, g + (size_t)(row0 + row) * ld + k0 + kq * 8);
    }
}
// fp16 tile loader: [64 rows x 32 k]
__device__ __forceinline__ void ldtileA64(u32 dstb, const f16* g, int row0, int ld, int k0, int t) {
    int row = t >> 2, kq = t & 3;
    cpa16(dstb + row * 80 + kq * 16, g + (size_t)(row0 + row) * ld + k0 + kq * 8);
}

#define TB 10240     // 128-row fp16 tile
#define ATB 5120     // 64-row fp16 tile
#define SSTG (ATB + 2 * TB)   // sage stage = 25600

// ---------------- fused sq + fp16 pack -----------------------------------------
__global__ void sqprep_kernel(const float* __restrict__ x) {
    int warp = (blockIdx.x * blockDim.x + threadIdx.x) >> 5;
    int lane = threadIdx.x & 31;
    if (warp >= NN) return;
    const float* r = x + (size_t)warp * FEA;
    float s = 0.f;
    #pragma unroll
    for (int q = 0; q < 2; q++) {
        int c4 = (lane + 32 * q) * 4;
        if (c4 < FEA) {
            float4 v = *(const float4*)(r + c4);
            s += v.x * v.x + v.y * v.y + v.z * v.z + v.w * v.w;
            __half2 p0; p0.x = __float2half_rn(v.x); p0.y = __float2half_rn(v.y);
            __half2 p1; p1.x = __float2half_rn(v.z); p1.y = __float2half_rn(v.w);
            size_t off = (size_t)warp * KSTR + 192 + c4;
            *(__half2*)(g_c0h + off)     = p0;
            *(__half2*)(g_c0h + off + 2) = p1;
        }
    }
    #pragma unroll
    for (int o = 16; o; o >>= 1) s += __shfl_xor_sync(0xffffffffu, s, o);
    if (lane == 0) g_sq[warp] = s;
}

// all weight builds in one launch
__global__ void wt_build_all(const float* __restrict__ Wl0, const float* __restrict__ Wr0,
                             const float* __restrict__ Wl1, const float* __restrict__ Wr1,
                             const float* __restrict__ Wl2, const float* __restrict__ Wr2) {
    int layer = blockIdx.y;
    int idx = blockIdx.x * 256 + threadIdx.x;
    if (layer == 0) {
        if (idx >= 256 * 384) return;
        int k = idx % 384, n = idx / 384;
        float v = (k < 192) ? Wl0[(size_t)k * HID + n] : Wr0[(size_t)(k - 192) * HID + n];
        f16 h, l; spltw(v, h, l);
        g_w0h[idx] = h; g_w0l[idx] = l;
    } else if (layer == 1) {
        if (idx >= 256 * 512) return;
        int k = idx % 512, n = idx / 512;
        float v = (k < 256) ? Wl1[(size_t)k * HID + n] : Wr1[(size_t)(k - 256) * HID + n];
        g_w1h[idx] = __float2half_rn(v);
    } else {
        if (idx >= 1024 * 512) return;
        int n = idx / 512, k = idx % 512;
        float v = 0.f;
        if (n < CLS) v = (k < 256) ? Wl2[(size_t)k * CLS + n] : Wr2[(size_t)(k - 256) * CLS + n];
        g_w2h[idx] = __float2half_rn(v);
    }
}

// ---------------- fp16 distance screen GEMM (triangular grid, M128) ------------
__global__ __launch_bounds__(256, 2) void dist_half(const f16* __restrict__ Xh) {
    int tp = blockIdx.x;
    int bj = (int)((sqrtf(8.f * tp + 1.f) - 1.f) * 0.5f);
    while ((bj + 1) * (bj + 2) / 2 <= tp) bj++;
    while (bj * (bj + 1) / 2 > tp) bj--;
    int bi = tp - bj * (bj + 1) / 2;

    extern __shared__ __align__(16) char smem[];
    u32 sb = s2u(smem);
    int t = threadIdx.x, lane = t & 31, warp = t >> 5;
    int wm = warp & 1, wn = warp >> 1;

    float acc[4][4][4] = {};

    const int NC = FEA / 32;   // 6
    ldtile(sb + 0 * TB, Xh, bi * 128, KSTR, 0, t);
    ldtile(sb + 1 * TB, Xh, bj * 128, KSTR, 0, t);
    asm volatile("cp.async.commit_group;");

    for (int c = 0; c < NC; c++) {
        if (c + 1 < NC) {
            u32 bb = sb + ((c + 1) & 1) * 2 * TB;
            int k0 = (c + 1) * 32;
            ldtile(bb + 0 * TB, Xh, bi * 128, KSTR, k0, t);
            ldtile(bb + 1 * TB, Xh, bj * 128, KSTR, k0, t);
            asm volatile("cp.async.commit_group;");
            asm volatile("cp.async.wait_group 1;");
        } else {
            asm volatile("cp.async.wait_group 0;");
        }
        __syncthreads();
        u32 base = sb + (c & 1) * 2 * TB;
        u32 aH = base, bH = base + TB;
        #pragma unroll
        for (int kk = 0; kk < 32; kk += 16) {
            u32 AH[4][4], BH[4][2];
            #pragma unroll
            for (int mt = 0; mt < 4; mt++) {
                u32 ro = (u32)((wm * 64 + mt * 16 + (lane & 15)) * 80 + (kk + (lane >> 4) * 8) * 2);
                ldsm4(AH[mt], aH + ro);
            }
            #pragma unroll
            for (int np = 0; np < 2; np++) {
                u32 ro = (u32)((wn * 32 + np * 16 + ((lane >> 4) * 8) + (lane & 7)) * 80
                               + (kk + ((lane >> 3) & 1) * 8) * 2);
                u32 r[4];
                ldsm4(r, bH + ro);
                BH[2 * np][0] = r[0]; BH[2 * np][1] = r[1];
                BH[2 * np + 1][0] = r[2]; BH[2 * np + 1][1] = r[3];
            }
            #pragma unroll
            for (int mt = 0; mt < 4; mt++)
                #pragma unroll
                for (int nt = 0; nt < 4; nt++)
                    mma16816(acc[mt][nt], AH[mt], BH[nt]);
        }
        __syncthreads();
    }

    u16* sD = (u16*)smem;            // [128][136]
    u16* sT = sD + 128 * 136;
    bool diag = (bi == bj);
    #pragma unroll
    for (int mt = 0; mt < 4; mt++) {
        int rl0 = wm * 64 + mt * 16 + (lane >> 2);
        #pragma unroll
        for (int nt = 0; nt < 4; nt++) {
            int cl = wn * 32 + nt * 8 + (lane & 3) * 2;
            float sqc0 = g_sq[bj * 128 + cl], sqc1 = g_sq[bj * 128 + cl + 1];
            #pragma unroll
            for (int h = 0; h < 2; h++) {
                int rl = rl0 + h * 8;
                float sr = g_sq[bi * 128 + rl];
                float d0 = sr + sqc0 - 2.f * acc[mt][nt][2 * h + 0];
                float d1 = sr + sqc1 - 2.f * acc[mt][nt][2 * h + 1];
                u16 b0 = __half_as_ushort(__float2half_rn(d0));
                u16 b1 = __half_as_ushort(__float2half_rn(d1));
                sD[rl * 136 + cl] = b0;
                sD[rl * 136 + cl + 1] = b1;
                if (!diag) {
                    sT[cl * 136 + rl] = b0;
                    sT[(cl + 1) * 136 + rl] = b1;
                }
            }
        }
    }
    __syncthreads();
    u16* gD = (u16*)g_Dh;
    for (int e = t; e < 128 * 16; e += 256) {
        int r = e >> 4, c8 = (e & 15) * 8;
        uint4 v = *(uint4*)&sD[r * 136 + c8];
        *(uint4*)(gD + (size_t)(bi * 128 + r) * NN + bj * 128 + c8) = v;
    }
    if (!diag) {
        for (int e = t; e < 128 * 16; e += 256) {
            int r = e >> 4, c8 = (e & 15) * 8;
            uint4 v = *(uint4*)&sT[r * 136 + c8];
            *(uint4*)(gD + (size_t)(bj * 128 + r) * NN + bi * 128 + c8) = v;
        }
    }

    {
        int r = t >> 1, hf = t & 1;
        const __half2* pr = (const __half2*)(sD + r * 136 + hf * 64);
        __half2 m2 = pr[0];
        #pragma unroll
        for (int q = 1; q < 32; q++) m2 = __hmin2(m2, pr[q]);
        float fm = fminf(__half2float(__low2half(m2)), __half2float(__high2half(m2)));
        float fo = __shfl_xor_sync(0xffffffffu, fm, 1);
        if (hf == 0)
            g_tmin[(size_t)(bi * 128 + r) * 64 + bj] = __float2half(fminf(fm, fo));
    }
    if (!diag) {
        int r = t >> 1, hf = t & 1;
        const __half2* pr = (const __half2*)(sT + r * 136 + hf * 64);
        __half2 m2 = pr[0];
        #pragma unroll
        for (int q = 1; q < 32; q++) m2 = __hmin2(m2, pr[q]);
        float fm = fminf(__half2float(__low2half(m2)), __half2float(__high2half(m2)));
        float fo = __shfl_xor_sync(0xffffffffu, fm, 1);
        if (hf == 0)
            g_tmin[(size_t)(bj * 128 + r) * 64 + bi] = __float2half(fminf(fm, fo));
    }
}

// ---------------- warp-per-row: compacted-tile screen + exact refine ------------
__global__ __launch_bounds__(256, 6) void topk_warp(const float* __restrict__ x) {
    int lane = threadIdx.x & 31, wid = threadIdx.x >> 5;
    int row = blockIdx.x * 8 + wid;

    __shared__ u32 slist[8][LCAP];
    __shared__ float scd[8][LCAP];
    __shared__ u16 satile[8][64];
    __shared__ int scnt[8];

    if (lane == 0) scnt[wid] = 0;
    __syncwarp();

    // ---- Phase A: threshold = 16th smallest of 64 tile mins ----
    const u16* tm = (const u16*)(g_tmin + (size_t)row * 64);
    u32 e0 = okey((u32)tm[lane]);
    u32 e1 = okey((u32)tm[lane + 32]);
    u32 k0 = (e0 << 6) | (u32)(lane << 1);
    u32 k1 = (e1 << 6) | (u32)(lane << 1) | 1u;
    u32 m16 = 0;
    #pragma unroll
    for (int r = 0; r < 16; r++) {
        u32 mn = min(k0, k1);
        #pragma unroll
        for (int o = 16; o; o >>= 1) mn = min(mn, __shfl_xor_sync(0xffffffffu, mn, o));
        m16 = mn;
        if (k0 == mn) k0 = 0xFFFFFFFFu;
        else if (k1 == mn) k1 = 0xFFFFFFFFu;
    }
    u32 thr_key = m16 >> 6;
    u32 thr_hb = (thr_key & 0x8000u) ? (thr_key ^ 0x8000u) : (thr_key ^ 0xFFFFu);
    __half2 thr2 = __half2half2(__ushort_as_half((u16)thr_hb));

    // compact surviving tile ids (lane owns tiles lane and lane+32)
    bool a0 = (e0 <= thr_key), a1 = (e1 <= thr_key);
    u32 b0 = __ballot_sync(0xffffffffu, a0);
    u32 b1 = __ballot_sync(0xffffffffu, a1);
    int n0 = __popc(b0);
    if (a0) satile[wid][__popc(b0 & ((1u << lane) - 1u))] = (u16)lane;
    if (a1) satile[wid][n0 + __popc(b1 & ((1u << lane) - 1u))] = (u16)(lane + 32);
    int A = n0 + __popc(b1);
    __syncwarp();

    // ---- Phase B: iterate only over active tiles (16 uint4 per tile) ----
    const uint4* rp = (const uint4*)(g_Dh + (size_t)row * NN);
    int total4 = A * 16;
    for (int q0 = 0; q0 < total4; q0 += 32) {
        int idx = q0 + lane;
        bool in = (idx < total4);
        bool need = false;
        uint4 v = make_uint4(0, 0, 0, 0);
        u32 u4 = 0;
        if (in) {
            int tile = (int)satile[wid][idx >> 4];
            u4 = (u32)(tile * 16 + (idx & 15));
            v = __ldg(rp + u4);
            union { u32 u; __half2 h; } a0u, a1u, a2u, a3u;
            a0u.u = v.x; a1u.u = v.y; a2u.u = v.z; a3u.u = v.w;
            __half2 mm = __hmin2(__hmin2(a0u.h, a1u.h), __hmin2(a2u.h, a3u.h));
            union { __half2 h; u32 u; } cc; cc.h = __hle2(mm, thr2);
            need = (cc.u != 0);
        }
        if (__ballot_sync(0xffffffffu, need)) {
            if (need) {
                u32 w[4] = {v.x, v.y, v.z, v.w};
                u32 base = u4 * 8;
                #pragma unroll
                for (int p = 0; p < 4; p++) {
                    #pragma unroll
                    for (int hh = 0; hh < 2; hh++) {
                        u32 key = okey((w[p] >> (16 * hh)) & 0xFFFFu);
                        if (key <= thr_key) {
                            int pos = atomicAdd(&scnt[wid], 1);
                            if (pos < LCAP)
                                slist[wid][pos] = (key << 16) | (base + p * 2 + hh);
                        }
                    }
                }
            }
        }
    }
    __syncwarp();
    int cnt = min(scnt[wid], LCAP);

    // ---- Phase C: exact fp32 refine ----
    float xi[6];
    const float* xr = x + (size_t)row * FEA;
    #pragma unroll
    for (int q = 0; q < 6; q++) xi[q] = __ldg(xr + q * 32 + lane);
    float sqi = g_sq[row];
    for (int c = 0; c < cnt; c++) {
        int j = (int)(slist[wid][c] & 0xFFFFu);
        const float* xj = x + (size_t)j * FEA;
        float s = 0.f;
        #pragma unroll
        for (int q = 0; q < 6; q++) s = fmaf(xi[q], __ldg(xj + q * 32 + lane), s);
        #pragma unroll
        for (int o = 16; o; o >>= 1) s += __shfl_xor_sync(0xffffffffu, s, o);
        if (lane == 0) scd[wid][c] = sqi + g_sq[j] - 2.f * s;
    }
    __syncwarp();

    // ---- Phase D: exact top-9 by (fp32 dist, idx) ----
    u64 mykeys[4];
    #pragma unroll
    for (int q = 0; q < 4; q++) {
        int c = lane + 32 * q;
        if (c < cnt) {
            u32 b = __float_as_uint(scd[wid][c]);
            b ^= (b & 0x80000000u) ? 0xFFFFFFFFu : 0x80000000u;
            mykeys[q] = ((u64)b << 32) | (u32)(slist[wid][c] & 0xFFFFu);
        } else {
            mykeys[q] = ~0ull;
        }
    }
    #pragma unroll
    for (int r = 0; r < KNB; r++) {
        u64 mn = mykeys[0];
        #pragma unroll
        for (int q = 1; q < 4; q++) mn = mykeys[q] < mn ? mykeys[q] : mn;
        #pragma unroll
        for (int o = 16; o; o >>= 1) {
            u64 other = __shfl_xor_sync(0xffffffffu, mn, o);
            mn = other < mn ? other : mn;
        }
        if (lane == 0) g_idx[row * KNB + r] = (int)(mn & 0xFFFFFFFFull);
        #pragma unroll
        for (int q = 0; q < 4; q++) if (mykeys[q] == mn) mykeys[q] = ~0ull;
        __syncwarp();
    }
}

// ---------------- gather + mean from fp32 x (layer 0) --------------------------
__global__ void gather_x(const float* __restrict__ x, f16* __restrict__ oh) {
    int row = blockIdx.x * 4 + threadIdx.y;
    int c4 = threadIdx.x * 4;
    const int* idp = g_idx + row * KNB;
    float4 s = make_float4(0.f, 0.f, 0.f, 0.f);
    #pragma unroll
    for (int j = 0; j < KNB; j++) {
        float4 v = __ldg((const float4*)(x + (size_t)idp[j] * FEA + c4));
        s.x += v.x; s.y += v.y; s.z += v.z; s.w += v.w;
    }
    const float inv = 1.0f / 9.0f;
    size_t off = (size_t)row * KSTR + c4;
    __half2 p0; p0.x = __float2half_rn(s.x * inv); p0.y = __float2half_rn(s.y * inv);
    __half2 p1; p1.x = __float2half_rn(s.z * inv); p1.y = __float2half_rn(s.w * inv);
    *(__half2*)(oh + off)     = p0;
    *(__half2*)(oh + off + 2) = p1;
}

// ---------------- gather + mean from fp16 cat self (layers 1,2) ----------------
__global__ void gather_f16(const f16* __restrict__ cat_self, f16* __restrict__ cat_agg) {
    int row = blockIdx.x * 8 + threadIdx.y;
    int c8 = threadIdx.x * 8;
    const int* idp = g_idx + row * KNB;
    float s[8] = {0.f, 0.f, 0.f, 0.f, 0.f, 0.f, 0.f, 0.f};
    #pragma unroll
    for (int j = 0; j < KNB; j++) {
        uint4 v = __ldg((const uint4*)(cat_self + (size_t)idp[j] * KSTR + c8));
        u32 w[4] = {v.x, v.y, v.z, v.w};
        #pragma unroll
        for (int p = 0; p < 4; p++) {
            float2 f = __half22float2(*(__half2*)&w[p]);
            s[2 * p] += f.x; s[2 * p + 1] += f.y;
        }
    }
    const float inv = 1.0f / 9.0f;
    u32 out[4];
    #pragma unroll
    for (int p = 0; p < 4; p++) {
        __half2 h; h.x = __float2half_rn(s[2 * p] * inv); h.y = __float2half_rn(s[2 * p + 1] * inv);
        out[p] = *(u32*)&h;
    }
    *(uint4*)(cat_agg + (size_t)row * KSTR + c8) = *(uint4*)out;
}

// ---------------- SAGE dual-GEMM, M64 tiles, 3 CTAs/SM --------------------------
template <bool TWOTERM>
__global__ __launch_bounds__(256, 3) void sage_mma(
    const f16* __restrict__ Ah, int Ktot,
    const f16* __restrict__ Bh, const f16* __restrict__ Bl,
    const float* __restrict__ bias, int Nbias,
    f16* __restrict__ Sh, float* __restrict__ part)
{
    int bn = blockIdx.x, bm = blockIdx.y;
    extern __shared__ __align__(16) char smem[];
    u32 sb = s2u(smem);
    int t = threadIdx.x, lane = t & 31, warp = t >> 5;
    int wm = warp & 1, wn = warp >> 1;

    float acc[2][4][4] = {};

    int nc = Ktot / 32;
    ldtileA64(sb + 0, Ah, bm * 64, KSTR, 0, t);
    ldtile(sb + ATB, Bh, bn * 128, Ktot, 0, t);
    if (TWOTERM) ldtile(sb + ATB + TB, Bl, bn * 128, Ktot, 0, t);
    asm volatile("cp.async.commit_group;");

    for (int c = 0; c < nc; c++) {
        if (c + 1 < nc) {
            u32 bb = sb + ((c + 1) & 1) * SSTG;
            int k0 = (c + 1) * 32;
            ldtileA64(bb + 0, Ah, bm * 64, KSTR, k0, t);
            ldtile(bb + ATB, Bh, bn * 128, Ktot, k0, t);
            if (TWOTERM) ldtile(bb + ATB + TB, Bl, bn * 128, Ktot, k0, t);
            asm volatile("cp.async.commit_group;");
            asm volatile("cp.async.wait_group 1;");
        } else {
            asm volatile("cp.async.wait_group 0;");
        }
        __syncthreads();
        u32 base = sb + (c & 1) * SSTG;
        u32 aH = base, bH = base + ATB, bL = base + ATB + TB;
        #pragma unroll
        for (int kk = 0; kk < 32; kk += 16) {
            u32 AH[2][4], BH[4][2], BL[4][2];
            #pragma unroll
            for (int mt = 0; mt < 2; mt++) {
                u32 ro = (u32)((wm * 32 + mt * 16 + (lane & 15)) * 80 + (kk + (lane >> 4) * 8) * 2);
                ldsm4(AH[mt], aH + ro);
            }
            #pragma unroll
            for (int np = 0; np < 2; np++) {
                u32 ro = (u32)((wn * 32 + np * 16 + ((lane >> 4) * 8) + (lane & 7)) * 80
                               + (kk + ((lane >> 3) & 1) * 8) * 2);
                u32 r[4];
                ldsm4(r, bH + ro);
                BH[2 * np][0] = r[0]; BH[2 * np][1] = r[1];
                BH[2 * np + 1][0] = r[2]; BH[2 * np + 1][1] = r[3];
                if (TWOTERM) {
                    ldsm4(r, bL + ro);
                    BL[2 * np][0] = r[0]; BL[2 * np][1] = r[1];
                    BL[2 * np + 1][0] = r[2]; BL[2 * np + 1][1] = r[3];
                }
            }
            #pragma unroll
            for (int mt = 0; mt < 2; mt++)
                #pragma unroll
                for (int nt = 0; nt < 4; nt++) {
                    mma16816(acc[mt][nt], AH[mt], BH[nt]);
                    if (TWOTERM) mma16816(acc[mt][nt], AH[mt], BL[nt]);
                }
        }
        __syncthreads();
    }

    if (Sh) {
        #pragma unroll
        for (int mt = 0; mt < 2; mt++) {
            int rl0 = wm * 32 + mt * 16 + (lane >> 2);
            #pragma unroll
            for (int nt = 0; nt < 4; nt++) {
                int cl = wn * 32 + nt * 8 + (lane & 3) * 2;
                int col = bn * 128 + cl;
                float b0 = bias[col], b1 = bias[col + 1];
                #pragma unroll
                for (int h = 0; h < 2; h++) {
                    int row = bm * 64 + rl0 + h * 8;
                    float v0 = fmaxf(acc[mt][nt][2 * h + 0] + b0, 0.f);
                    float v1 = fmaxf(acc[mt][nt][2 * h + 1] + b1, 0.f);
                    __half2 p; p.x = __float2half_rn(v0); p.y = __float2half_rn(v1);
                    *(__half2*)(Sh + (size_t)row * KSTR + col) = p;
                }
            }
        }
    } else {
        float* sCol = (float*)smem;
        if (t < 128) sCol[t] = 0.f;
        __syncthreads();
        #pragma unroll
        for (int nt = 0; nt < 4; nt++) {
            int cl = wn * 32 + nt * 8 + (lane & 3) * 2;
            int col = bn * 128 + cl;
            float b0 = (col < Nbias) ? bias[col] : 0.f;
            float b1 = (col + 1 < Nbias) ? bias[col + 1] : 0.f;
            float p0 = 0.f, p1 = 0.f;
            #pragma unroll
            for (int mt = 0; mt < 2; mt++)
                #pragma unroll
                for (int h = 0; h < 2; h++) {
                    p0 += fmaxf(acc[mt][nt][2 * h + 0] + b0, 0.f);
                    p1 += fmaxf(acc[mt][nt][2 * h + 1] + b1, 0.f);
                }
            atomicAdd(&sCol[cl], p0);
            atomicAdd(&sCol[cl + 1], p1);
        }
        __syncthreads();
        if (t < 128) part[(size_t)(bm * 8 + bn) * 128 + t] = sCol[t];
    }
}

// ---------------- pool reduce ----------------------------------------------------
__global__ void reduce_pool(float* __restrict__ out) {
    int idx = blockIdx.x * 256 + threadIdx.x;
    if (idx >= BATCH * CLS) return;
    int b = idx / CLS, o = idx % CLS;
    int bn = o >> 7, c = o & 127;
    float s = 0.f;
    #pragma unroll
    for (int q = 0; q < 8; q++)
        s += g_part[(size_t)((b * 8 + q) * 8 + bn) * 128 + c];
    out[idx] = s * (1.0f / 512.0f);
}

// ---------------- launch --------------------------------------------------------
#define DIST_SMEM (128 * 136 * 2 * 2)   // 69632
#define SAGE_SMEM (2 * SSTG)            // 51200

extern "C" void kernel_launch(void* const* d_in, const int* in_sizes, int n_in,
                              void* d_out, int out_size) {
    const float* x   = (const float*)d_in[0];
    const float* wl0 = (const float*)d_in[1];
    const float* bl0 = (const float*)d_in[2];
    const float* wr0 = (const float*)d_in[3];
    const float* wl1 = (const float*)d_in[4];
    const float* bl1 = (const float*)d_in[5];
    const float* wr1 = (const float*)d_in[6];
    const float* wl2 = (const float*)d_in[7];
    const float* bl2 = (const float*)d_in[8];
    const float* wr2 = (const float*)d_in[9];
    float* out = (float*)d_out;

    f16 *c0h, *c1h, *w0h, *w0l, *w1h, *w2h;
    float* part;
    cudaGetSymbolAddress((void**)&c0h, g_c0h);
    cudaGetSymbolAddress((void**)&c1h, g_c1h);
    cudaGetSymbolAddress((void**)&w0h, g_w0h);
    cudaGetSymbolAddress((void**)&w0l, g_w0l);
    cudaGetSymbolAddress((void**)&w1h, g_w1h);
    cudaGetSymbolAddress((void**)&w2h, g_w2h);
    cudaGetSymbolAddress((void**)&part, g_part);

    cudaFuncSetAttribute(dist_half, cudaFuncAttributeMaxDynamicSharedMemorySize, DIST_SMEM);
    cudaFuncSetAttribute(sage_mma<true>, cudaFuncAttributeMaxDynamicSharedMemorySize, SAGE_SMEM);
    cudaFuncSetAttribute(sage_mma<false>, cudaFuncAttributeMaxDynamicSharedMemorySize, SAGE_SMEM);

    sqprep_kernel<<<NN / 8, 256>>>(x);                                  // 1
    wt_build_all<<<dim3(2048, 3), 256>>>(wl0, wr0, wl1, wr1, wl2, wr2); // 2
    dist_half<<<2080, 256, DIST_SMEM>>>(c0h + 192);                     // 3
    topk_warp<<<NN / 8, 256>>>(x);                                      // 4 (profiled)

    // layer 0: c0h = [agg(x) | x], K=384, 2-term weights
    gather_x<<<NN / 4, dim3(FEA / 4, 4)>>>(x, c0h);
    sage_mma<true><<<dim3(2, 128), 256, SAGE_SMEM>>>(c0h, 384, w0h, w0l, bl0, HID,
                                                     c1h + 256, nullptr);
    // layer 1: c1h = [agg(h1) | h1], K=512, hi-only weights
    gather_f16<<<NN / 8, dim3(32, 8)>>>(c1h + 256, c1h);
    sage_mma<false><<<dim3(2, 128), 256, SAGE_SMEM>>>(c1h, 512, w1h, nullptr, bl1, HID,
                                                      c0h + 256, nullptr);
    // layer 2: c0h = [agg(h2) | h2], K=512, N padded 1024, hi-only weights
    gather_f16<<<NN / 8, dim3(32, 8)>>>(c0h + 256, c0h);
    sage_mma<false><<<dim3(8, 128), 256, SAGE_SMEM>>>(c0h, 512, w2h, nullptr, bl2, CLS,
                                                      nullptr, part);

    reduce_pool<<<(BATCH * CLS + 255) / 256, 256>>>(out);
}